// round 6
// baseline (speedup 1.0000x reference)
#include <cuda_runtime.h>

// Problem dims
#define B_  64
#define T_  2048
#define E_  256
#define A_  128
#define P_  128
#define R_  1024
#define D_  1024
#define H_  256
#define F_  32
#define KS_ 31
#define PAD_ 15

// ---------------- scratch (no allocations allowed) ----------------
__device__ float g_gates[B_ * 4096];
__device__ float g_ah[B_ * R_];
__device__ float g_ac[B_ * R_];
__device__ float g_pq[B_ * A_];
__device__ float g_energies[B_ * T_];
__device__ float g_ctx[B_ * E_];
__device__ float g_dh[B_ * D_];
__device__ float g_dc[B_ * D_];
__device__ float g_conv[(size_t)B_ * T_ * F_];   // [b][t][f]

// ---------------- helpers ----------------
__device__ __forceinline__ unsigned f2tf(float f) {
    unsigned u;
    asm("cvt.rna.tf32.f32 %0, %1;" : "=r"(u) : "f"(f));
    return u;
}

__device__ __forceinline__ void mma_tf32(float* c,
    unsigned a0, unsigned a1, unsigned a2, unsigned a3,
    unsigned b0, unsigned b1)
{
    asm volatile(
        "mma.sync.aligned.m16n8k8.row.col.f32.tf32.tf32.f32 "
        "{%0,%1,%2,%3}, {%4,%5,%6,%7}, {%8,%9}, {%0,%1,%2,%3};"
        : "+f"(c[0]), "+f"(c[1]), "+f"(c[2]), "+f"(c[3])
        : "r"(a0), "r"(a1), "r"(a2), "r"(a3), "r"(b0), "r"(b1));
}

__device__ __forceinline__ float sigm(float x) { return 1.f / (1.f + __expf(-x)); }
__device__ __forceinline__ float fast_tanh(float x) {
    float e = __expf(2.f * x);
    return 1.f - __fdividef(2.f, e + 1.f);
}

// ---------------- tf32 MMA 3-segment GEMM: C[64,N] = sum_s x_s @ W_s^T + b1 + b2
// BM=64, BN=32, BK=32. 128 threads = 4 warps; warp w owns n-slice w*8..w*8+7.
// Segment K's must be multiples of 32; N multiple of 32.
__global__ __launch_bounds__(128) void mma_gemm3(
    const float* __restrict__ x1, const float* __restrict__ W1, int K1, int ld1,
    const float* __restrict__ x2, const float* __restrict__ W2, int K2, int ld2,
    const float* __restrict__ x3, const float* __restrict__ W3, int K3, int ld3,
    const float* __restrict__ b1, const float* __restrict__ b2,
    float* __restrict__ C, int N)
{
    __shared__ unsigned As[64][36];   // tf32 bits, [m][k], pad 36 -> conflict-free frags
    __shared__ unsigned Ws[32][36];   // tf32 bits, [n][k]

    const int tid  = threadIdx.x;
    const int lane = tid & 31;
    const int w    = tid >> 5;
    const int gid  = lane >> 2;   // 0..7
    const int tig  = lane & 3;    // 0..3
    const int n0   = blockIdx.x * 32;

    float acc[4][4] = {};   // 4 m-tiles (16 rows each) x 4 C regs

#pragma unroll
    for (int s = 0; s < 3; s++) {
        const float* x  = (s == 0) ? x1 : (s == 1) ? x2 : x3;
        const float* W  = (s == 0) ? W1 : (s == 1) ? W2 : W3;
        const int K     = (s == 0) ? K1 : (s == 1) ? K2 : K3;
        const int ld    = (s == 0) ? ld1 : (s == 1) ? ld2 : ld3;
        if (K == 0) continue;
        for (int k0 = 0; k0 < K; k0 += 32) {
            // A tile 64x32: 512 float4, 4 per thread
#pragma unroll
            for (int r = 0; r < 4; r++) {
                int j = tid + r * 128;
                int m = j >> 3, kq = j & 7;
                float4 v = *(const float4*)(x + (size_t)m * K + k0 + kq * 4);
                uint4 u = { f2tf(v.x), f2tf(v.y), f2tf(v.z), f2tf(v.w) };
                *(uint4*)&As[m][kq * 4] = u;
            }
            // B tile 32x32: 256 float4, 2 per thread
#pragma unroll
            for (int r = 0; r < 2; r++) {
                int j = tid + r * 128;
                int n = j >> 3, kq = j & 7;
                float4 v = *(const float4*)(W + (size_t)(n0 + n) * ld + k0 + kq * 4);
                uint4 u = { f2tf(v.x), f2tf(v.y), f2tf(v.z), f2tf(v.w) };
                *(uint4*)&Ws[n][kq * 4] = u;
            }
            __syncthreads();
#pragma unroll
            for (int kk = 0; kk < 32; kk += 8) {
                unsigned bb0 = Ws[w * 8 + gid][kk + tig];
                unsigned bb1 = Ws[w * 8 + gid][kk + tig + 4];
#pragma unroll
                for (int mt = 0; mt < 4; mt++) {
                    int ra = mt * 16 + gid;
                    unsigned a0 = As[ra][kk + tig];
                    unsigned a1 = As[ra + 8][kk + tig];
                    unsigned a2 = As[ra][kk + tig + 4];
                    unsigned a3 = As[ra + 8][kk + tig + 4];
                    mma_tf32(acc[mt], a0, a1, a2, a3, bb0, bb1);
                }
            }
            __syncthreads();
        }
    }

    // epilogue: c0 (gid, tig*2), c1 (gid, tig*2+1), c2 (gid+8, ...), c3
    int n = n0 + w * 8 + tig * 2;
    float add0 = (b1 ? b1[n] : 0.f) + (b2 ? b2[n] : 0.f);
    float add1 = (b1 ? b1[n + 1] : 0.f) + (b2 ? b2[n + 1] : 0.f);
#pragma unroll
    for (int mt = 0; mt < 4; mt++) {
        int ra = mt * 16 + gid, rb = ra + 8;
        C[(size_t)ra * N + n]     = acc[mt][0] + add0;
        C[(size_t)ra * N + n + 1] = acc[mt][1] + add1;
        C[(size_t)rb * N + n]     = acc[mt][2] + add0;
        C[(size_t)rb * N + n + 1] = acc[mt][3] + add1;
    }
}

// ---------------- LSTM pointwise ----------------
__global__ void lstm_pointwise(const float* __restrict__ gates,
                               const float* __restrict__ c_prev,
                               float* __restrict__ h_out, float* __restrict__ c_out,
                               int Nc)
{
    int idx = blockIdx.x * blockDim.x + threadIdx.x;
    if (idx >= B_ * Nc) return;
    int b = idx / Nc, j = idx - b * Nc;
    const float* g = gates + (size_t)b * 4 * Nc;
    float gi = sigm(g[j]);
    float gf = sigm(g[Nc + j]);
    float gg = fast_tanh(g[2 * Nc + j]);
    float go = sigm(g[3 * Nc + j]);
    float c2 = gf * c_prev[idx] + gi * gg;
    h_out[idx] = go * fast_tanh(c2);
    c_out[idx] = c2;
}

// ---------------- conv31 over (att_w, att_w_cum) -> g_conv[b][t][f] ----------------
// grid (T/64, B), 128 threads: thread = (f = tid&31, tg = tid>>5), 16 t's each.
__global__ __launch_bounds__(128) void conv_kernel(
    const float* __restrict__ att_w, const float* __restrict__ att_w_cum,
    const float* __restrict__ W_loc, float* __restrict__ conv_out)
{
    const int b  = blockIdx.y;
    const int t0 = blockIdx.x * 64;
    const int tid = threadIdx.x;

    __shared__ float s_aw[2][94];
    __shared__ float s_w[F_ * 2 * KS_];

    for (int i = tid; i < 94; i += 128) {
        int g = t0 - PAD_ + i;
        bool ok = (g >= 0) && (g < T_);
        s_aw[0][i] = ok ? att_w[b * T_ + g] : 0.f;
        s_aw[1][i] = ok ? att_w_cum[b * T_ + g] : 0.f;
    }
    for (int i = tid; i < F_ * 2 * KS_; i += 128) s_w[i] = W_loc[i];
    __syncthreads();

    int f = tid & 31, tg = tid >> 5;
    float acc[16];
#pragma unroll
    for (int i = 0; i < 16; i++) acc[i] = 0.f;
#pragma unroll
    for (int c = 0; c < 2; c++) {
        float av[46];
#pragma unroll
        for (int i = 0; i < 46; i++) av[i] = s_aw[c][tg * 16 + i];
#pragma unroll
        for (int k = 0; k < KS_; k++) {
            float wv = s_w[(f * 2 + c) * KS_ + k];
#pragma unroll
            for (int tt = 0; tt < 16; tt++) acc[tt] += wv * av[k + tt];
        }
    }
#pragma unroll
    for (int tt = 0; tt < 16; tt++)
        conv_out[(size_t)(b * T_ + t0 + tg * 16 + tt) * F_ + f] = acc[tt];
}

// ---------------- energy: tanh(pq + pm + conv@lfc) . W_v -> energies[b][t] ----------------
// grid (T/64, B), 128 threads (a = tid). Warp-shuffle reduce over a.
__global__ __launch_bounds__(128) void energy_kernel(
    const float* __restrict__ conv_in,  // [b][t][f]
    const float* __restrict__ pm,       // [B,T,A]
    const float* __restrict__ pq,       // [B,A]
    const float* __restrict__ W_lfc,    // [A,F]
    const float* __restrict__ W_v,      // [A]
    float* __restrict__ energies)       // [B,T]
{
    const int b   = blockIdx.y;
    const int t0  = blockIdx.x * 64;
    const int tid = threadIdx.x;
    const int wid = tid >> 5, lane = tid & 31;

    __shared__ float s_cv[64][32];
    __shared__ float s_part[4][64];

    const float4* src = (const float4*)(conv_in + (size_t)(b * T_ + t0) * F_);
#pragma unroll
    for (int r = 0; r < 4; r++)
        ((float4*)s_cv)[tid + r * 128] = src[tid + r * 128];

    float r_lfc[32];
    const float4* lf4 = (const float4*)(W_lfc + tid * F_);
#pragma unroll
    for (int i = 0; i < 8; i++) {
        float4 v = lf4[i];
        r_lfc[i * 4] = v.x; r_lfc[i * 4 + 1] = v.y;
        r_lfc[i * 4 + 2] = v.z; r_lfc[i * 4 + 3] = v.w;
    }
    float r_pq = pq[b * A_ + tid];
    float r_wv = W_v[tid];
    const float* pmb = pm + ((size_t)b * T_ + t0) * A_ + tid;
    __syncthreads();

#pragma unroll 2
    for (int t = 0; t < 64; t++) {
        float la = 0.f;
#pragma unroll
        for (int q = 0; q < 8; q++) {
            float4 cv = *(const float4*)&s_cv[t][q * 4];
            la += cv.x * r_lfc[4 * q]     + cv.y * r_lfc[4 * q + 1]
                + cv.z * r_lfc[4 * q + 2] + cv.w * r_lfc[4 * q + 3];
        }
        float v = fast_tanh(r_pq + pmb[(size_t)t * A_] + la) * r_wv;
#pragma unroll
        for (int o = 16; o; o >>= 1) v += __shfl_xor_sync(0xffffffffu, v, o);
        if (lane == 0) s_part[wid][t] = v;
    }
    __syncthreads();
    if (tid < 64)
        energies[b * T_ + t0 + tid] =
            s_part[0][tid] + s_part[1][tid] + s_part[2][tid] + s_part[3][tid];
}

// ---------------- masked softmax over T (mask int32) ----------------
__global__ __launch_bounds__(256) void softmax_kernel(
    const float* __restrict__ energies, const int* __restrict__ mask,
    float* __restrict__ weights)
{
    int b = blockIdx.x, tid = threadIdx.x;
    __shared__ float red[8];
    __shared__ float s_bcast;
    float v[8];
    float mx = -3.4e38f;
#pragma unroll
    for (int r = 0; r < 8; r++) {
        int t = tid + r * 256;
        float e = energies[b * T_ + t];
        if (mask[b * T_ + t] != 0) e = -1e30f;
        v[r] = e;
        mx = fmaxf(mx, e);
    }
#pragma unroll
    for (int o = 16; o; o >>= 1) mx = fmaxf(mx, __shfl_xor_sync(0xffffffffu, mx, o));
    if ((tid & 31) == 0) red[tid >> 5] = mx;
    __syncthreads();
    if (tid < 8) {
        float m = red[tid];
#pragma unroll
        for (int o = 4; o; o >>= 1) m = fmaxf(m, __shfl_xor_sync(0xffu, m, o));
        if (tid == 0) s_bcast = m;
    }
    __syncthreads();
    mx = s_bcast;
    float sum = 0.f;
#pragma unroll
    for (int r = 0; r < 8; r++) { v[r] = __expf(v[r] - mx); sum += v[r]; }
#pragma unroll
    for (int o = 16; o; o >>= 1) sum += __shfl_xor_sync(0xffffffffu, sum, o);
    if ((tid & 31) == 0) red[tid >> 5] = sum;
    __syncthreads();
    if (tid < 8) {
        float m = red[tid];
#pragma unroll
        for (int o = 4; o; o >>= 1) m += __shfl_xor_sync(0xffu, m, o);
        if (tid == 0) s_bcast = m;
    }
    __syncthreads();
    float inv = 1.f / s_bcast;
#pragma unroll
    for (int r = 0; r < 8; r++) weights[b * T_ + tid + r * 256] = v[r] * inv;
}

// ---------------- context ----------------
__global__ void zero_kernel(float* p)
{
    p[blockIdx.x * blockDim.x + threadIdx.x] = 0.f;
}

__global__ __launch_bounds__(256) void ctx_kernel(
    const float* __restrict__ weights, const float* __restrict__ memory,
    float* __restrict__ ctx)
{
    int b = blockIdx.y;
    int t0 = blockIdx.x * 128;
    int e = threadIdx.x;
    const float* mb = memory + ((size_t)b * T_ + t0) * E_ + e;
    const float* wb = weights + b * T_ + t0;
    float acc = 0.f;
#pragma unroll 4
    for (int t = 0; t < 128; t++) acc += wb[t] * mb[(size_t)t * E_];
    atomicAdd(&ctx[b * E_ + e], acc);
}

// ---------------- stop gate: out[r] = [dh|ctx][r] . W_gate + b ----------------
__global__ __launch_bounds__(1024) void gate_kernel(
    const float* __restrict__ dh, const float* __restrict__ ctx,
    const float* __restrict__ W_gate, const float* __restrict__ b_gate,
    float* __restrict__ out_stop)
{
    int gtid = blockIdx.x * 1024 + threadIdx.x;
    int r = gtid >> 5, lane = gtid & 31;
    float acc = 0.f;
    const float* xr = dh + (size_t)r * D_;
#pragma unroll 4
    for (int k = lane; k < D_; k += 32) acc += xr[k] * W_gate[k];
    const float* cr = ctx + (size_t)r * E_;
#pragma unroll 4
    for (int k = lane; k < E_; k += 32) acc += cr[k] * W_gate[D_ + k];
#pragma unroll
    for (int o = 16; o; o >>= 1) acc += __shfl_xor_sync(0xffffffffu, acc, o);
    if (lane == 0) out_stop[r] = acc + b_gate[0];
}

// ---------------- launch ----------------
extern "C" void kernel_launch(void* const* d_in, const int* in_sizes, int n_in,
                              void* d_out, int out_size)
{
    const float* last_frame = (const float*)d_in[0];
    const float* att_h      = (const float*)d_in[1];
    const float* att_c      = (const float*)d_in[2];
    const float* att_w      = (const float*)d_in[3];
    const float* att_w_cum  = (const float*)d_in[4];
    const float* att_ctx    = (const float*)d_in[5];
    const float* dec_h      = (const float*)d_in[6];
    const float* dec_c      = (const float*)d_in[7];
    const float* memory     = (const float*)d_in[8];
    const float* pmem       = (const float*)d_in[9];
    const float* W_ih_a     = (const float*)d_in[10];
    const float* W_hh_a     = (const float*)d_in[11];
    const float* b_ih_a     = (const float*)d_in[12];
    const float* b_hh_a     = (const float*)d_in[13];
    const float* W_q        = (const float*)d_in[14];
    const float* W_v        = (const float*)d_in[15];
    const float* W_loc      = (const float*)d_in[16];
    const float* W_lfc      = (const float*)d_in[17];
    const float* W_ih_d     = (const float*)d_in[18];
    const float* W_hh_d     = (const float*)d_in[19];
    const float* b_ih_d     = (const float*)d_in[20];
    const float* b_hh_d     = (const float*)d_in[21];
    const float* W_proj     = (const float*)d_in[22];
    const float* b_proj     = (const float*)d_in[23];
    const float* W_gate     = (const float*)d_in[24];
    const float* b_gate     = (const float*)d_in[25];
    const int*   mask       = (const int*)d_in[26];

    float* out = (float*)d_out;
    float* out_proj = out;                      // [64,256]
    float* out_stop = out + B_ * H_;            // [64,1]
    float* out_w    = out + B_ * H_ + B_;       // [64,2048]

    float *gates, *ah, *ac, *pq, *energies, *ctx, *dh, *dc, *conv;
    cudaGetSymbolAddress((void**)&gates,    g_gates);
    cudaGetSymbolAddress((void**)&ah,       g_ah);
    cudaGetSymbolAddress((void**)&ac,       g_ac);
    cudaGetSymbolAddress((void**)&pq,       g_pq);
    cudaGetSymbolAddress((void**)&energies, g_energies);
    cudaGetSymbolAddress((void**)&ctx,      g_ctx);
    cudaGetSymbolAddress((void**)&dh,       g_dh);
    cudaGetSymbolAddress((void**)&dc,       g_dc);
    cudaGetSymbolAddress((void**)&conv,     g_conv);

    // conv (independent of LSTM) first
    conv_kernel<<<dim3(T_ / 64, B_), 128>>>(att_w, att_w_cum, W_loc, conv);

    // 1) attention LSTM gates (tf32 MMA)
    mma_gemm3<<<128, 128>>>(last_frame, W_ih_a,       P_, P_ + E_,
                            att_ctx,    W_ih_a + P_,  E_, P_ + E_,
                            att_h,      W_hh_a,       R_, R_,
                            b_ih_a, b_hh_a, gates, 4 * R_);
    lstm_pointwise<<<(B_ * R_) / 256, 256>>>(gates, att_c, ah, ac, R_);

    // 2) query projection pq = ah @ W_q^T
    mma_gemm3<<<A_ / 32, 128>>>(ah, W_q, R_, R_,
                                nullptr, nullptr, 0, 0,
                                nullptr, nullptr, 0, 0,
                                nullptr, nullptr, pq, A_);

    // 3) energies + softmax
    energy_kernel<<<dim3(T_ / 64, B_), 128>>>(conv, pmem, pq, W_lfc, W_v, energies);
    softmax_kernel<<<B_, 256>>>(energies, mask, out_w);

    // 4) context
    zero_kernel<<<B_, E_>>>(ctx);
    ctx_kernel<<<dim3(16, B_), 256>>>(out_w, memory, ctx);

    // 5) decoder LSTM gates (tf32 MMA)
    mma_gemm3<<<128, 128>>>(ah,    W_ih_d,       R_, R_ + E_,
                            ctx,   W_ih_d + R_,  E_, R_ + E_,
                            dec_h, W_hh_d,       D_, D_,
                            b_ih_d, b_hh_d, gates, 4 * D_);
    lstm_pointwise<<<(B_ * D_) / 256, 256>>>(gates, dec_c, dh, dc, D_);

    // 6) output heads
    mma_gemm3<<<H_ / 32, 128>>>(dh,  W_proj,       D_, D_ + E_,
                                ctx, W_proj + D_,  E_, D_ + E_,
                                nullptr, nullptr, 0, 0,
                                b_proj, nullptr, out_proj, H_);
    gate_kernel<<<2, 1024>>>(dh, ctx, W_gate, b_gate, out_stop);
}

// round 7
// speedup vs baseline: 2.0003x; 2.0003x over previous
#include <cuda_runtime.h>

// Problem dims
#define B_  64
#define T_  2048
#define E_  256
#define A_  128
#define P_  128
#define R_  1024
#define D_  1024
#define H_  256
#define F_  32
#define KS_ 31
#define PAD_ 15

// ---------------- scratch (no allocations allowed) ----------------
__device__ float g_gates[B_ * 4096];
__device__ float g_ah[B_ * R_];
__device__ float g_ac[B_ * R_];
__device__ float g_pq[B_ * A_];
__device__ float g_energies[B_ * T_];
__device__ float g_ctx[B_ * E_];
__device__ float g_dh[B_ * D_];
__device__ float g_dc[B_ * D_];
__device__ float g_conv[(size_t)B_ * T_ * F_];   // [b][t][f]

// ---------------- helpers ----------------
__device__ __forceinline__ unsigned f2tf(float f) {
    unsigned u;
    asm("cvt.rna.tf32.f32 %0, %1;" : "=r"(u) : "f"(f));
    return u;
}

__device__ __forceinline__ void mma_tf32(float* c,
    unsigned a0, unsigned a1, unsigned a2, unsigned a3,
    unsigned b0, unsigned b1)
{
    asm volatile(
        "mma.sync.aligned.m16n8k8.row.col.f32.tf32.tf32.f32 "
        "{%0,%1,%2,%3}, {%4,%5,%6,%7}, {%8,%9}, {%0,%1,%2,%3};"
        : "+f"(c[0]), "+f"(c[1]), "+f"(c[2]), "+f"(c[3])
        : "r"(a0), "r"(a1), "r"(a2), "r"(a3), "r"(b0), "r"(b1));
}

__device__ __forceinline__ void cp16(void* smem_dst, const void* gsrc) {
    unsigned dst = (unsigned)__cvta_generic_to_shared(smem_dst);
    asm volatile("cp.async.ca.shared.global [%0], [%1], 16;"
                 :: "r"(dst), "l"(gsrc));
}
__device__ __forceinline__ void cp_commit() {
    asm volatile("cp.async.commit_group;");
}
__device__ __forceinline__ void cp_wait1() {
    asm volatile("cp.async.wait_group 1;");
}

__device__ __forceinline__ float sigm(float x) { return 1.f / (1.f + __expf(-x)); }
__device__ __forceinline__ float fast_tanh(float x) {
    float e = __expf(2.f * x);
    return 1.f - __fdividef(2.f, e + 1.f);
}

// ---------------- tf32 MMA 3-segment GEMM, 3-stage cp.async pipeline ----------------
// C[64,N] = sum_s x_s @ W_s^T + b1 + b2. BM=64, BN=32, BK=32, 128 threads (4 warps).
// Segment K's must be multiples of 32; N multiple of 32.
__global__ __launch_bounds__(128) void mma_gemm3(
    const float* __restrict__ x1, const float* __restrict__ W1, int K1, int ld1,
    const float* __restrict__ x2, const float* __restrict__ W2, int K2, int ld2,
    const float* __restrict__ x3, const float* __restrict__ W3, int K3, int ld3,
    const float* __restrict__ b1, const float* __restrict__ b2,
    float* __restrict__ C, int N)
{
    __shared__ float As[3][64][36];   // fp32 tiles, pad 36 (row stride 144B, 16B-aligned)
    __shared__ float Ws[3][32][36];

    const int tid  = threadIdx.x;
    const int lane = tid & 31;
    const int w    = tid >> 5;
    const int gid  = lane >> 2;   // 0..7
    const int tig  = lane & 3;    // 0..3
    const int n0   = blockIdx.x * 32;

    float acc[4][4] = {};   // 4 m-tiles (16 rows) x 4 C regs

#pragma unroll
    for (int s = 0; s < 3; s++) {
        const float* x  = (s == 0) ? x1 : (s == 1) ? x2 : x3;
        const float* W  = (s == 0) ? W1 : (s == 1) ? W2 : W3;
        const int K     = (s == 0) ? K1 : (s == 1) ? K2 : K3;
        const int ld    = (s == 0) ? ld1 : (s == 1) ? ld2 : ld3;
        if (K == 0) continue;
        const int nt = K >> 5;

        __syncthreads();   // protect buffers from previous segment's last computes

        // issue tile `tile` into buffer `buf`
        auto issue = [&](int tile, int buf) {
            int k0 = tile * 32;
#pragma unroll
            for (int r = 0; r < 4; r++) {
                int j = tid + r * 128;
                int m = j >> 3, kq = j & 7;
                cp16(&As[buf][m][kq * 4], x + (size_t)m * K + k0 + kq * 4);
            }
#pragma unroll
            for (int r = 0; r < 2; r++) {
                int j = tid + r * 128;
                int n = j >> 3, kq = j & 7;
                cp16(&Ws[buf][n][kq * 4], W + (size_t)(n0 + n) * ld + k0 + kq * 4);
            }
        };

        // prologue: stages 0,1
        issue(0, 0);
        cp_commit();
        if (nt > 1) issue(1, 1);
        cp_commit();

        for (int it = 0; it < nt; it++) {
            cp_wait1();          // own groups: tile `it` landed
            __syncthreads();     // all threads' copies for tile `it` visible; all done computing it-1
            int nx = it + 2;
            if (nx < nt) issue(nx, nx % 3);
            cp_commit();         // keep group count uniform

            const int buf = it % 3;
#pragma unroll
            for (int kk = 0; kk < 32; kk += 8) {
                unsigned bb0 = f2tf(Ws[buf][w * 8 + gid][kk + tig]);
                unsigned bb1 = f2tf(Ws[buf][w * 8 + gid][kk + tig + 4]);
#pragma unroll
                for (int mt = 0; mt < 4; mt++) {
                    int ra = mt * 16 + gid;
                    unsigned a0 = f2tf(As[buf][ra][kk + tig]);
                    unsigned a1 = f2tf(As[buf][ra + 8][kk + tig]);
                    unsigned a2 = f2tf(As[buf][ra][kk + tig + 4]);
                    unsigned a3 = f2tf(As[buf][ra + 8][kk + tig + 4]);
                    mma_tf32(acc[mt], a0, a1, a2, a3, bb0, bb1);
                }
            }
        }
    }

    // epilogue
    int n = n0 + w * 8 + tig * 2;
    float add0 = (b1 ? b1[n] : 0.f) + (b2 ? b2[n] : 0.f);
    float add1 = (b1 ? b1[n + 1] : 0.f) + (b2 ? b2[n + 1] : 0.f);
#pragma unroll
    for (int mt = 0; mt < 4; mt++) {
        int ra = mt * 16 + gid, rb = ra + 8;
        C[(size_t)ra * N + n]     = acc[mt][0] + add0;
        C[(size_t)ra * N + n + 1] = acc[mt][1] + add1;
        C[(size_t)rb * N + n]     = acc[mt][2] + add0;
        C[(size_t)rb * N + n + 1] = acc[mt][3] + add1;
    }
}

// ---------------- LSTM pointwise ----------------
__global__ void lstm_pointwise(const float* __restrict__ gates,
                               const float* __restrict__ c_prev,
                               float* __restrict__ h_out, float* __restrict__ c_out,
                               int Nc)
{
    int idx = blockIdx.x * blockDim.x + threadIdx.x;
    if (idx >= B_ * Nc) return;
    int b = idx / Nc, j = idx - b * Nc;
    const float* g = gates + (size_t)b * 4 * Nc;
    float gi = sigm(g[j]);
    float gf = sigm(g[Nc + j]);
    float gg = fast_tanh(g[2 * Nc + j]);
    float go = sigm(g[3 * Nc + j]);
    float c2 = gf * c_prev[idx] + gi * gg;
    h_out[idx] = go * fast_tanh(c2);
    c_out[idx] = c2;
}

// ---------------- conv31 over (att_w, att_w_cum) -> g_conv[b][t][f] ----------------
__global__ __launch_bounds__(128) void conv_kernel(
    const float* __restrict__ att_w, const float* __restrict__ att_w_cum,
    const float* __restrict__ W_loc, float* __restrict__ conv_out)
{
    const int b  = blockIdx.y;
    const int t0 = blockIdx.x * 64;
    const int tid = threadIdx.x;

    __shared__ float s_aw[2][94];
    __shared__ float s_w[F_ * 2 * KS_];

    for (int i = tid; i < 94; i += 128) {
        int g = t0 - PAD_ + i;
        bool ok = (g >= 0) && (g < T_);
        s_aw[0][i] = ok ? att_w[b * T_ + g] : 0.f;
        s_aw[1][i] = ok ? att_w_cum[b * T_ + g] : 0.f;
    }
    for (int i = tid; i < F_ * 2 * KS_; i += 128) s_w[i] = W_loc[i];
    __syncthreads();

    int f = tid & 31, tg = tid >> 5;
    float acc[16];
#pragma unroll
    for (int i = 0; i < 16; i++) acc[i] = 0.f;
#pragma unroll
    for (int c = 0; c < 2; c++) {
        float av[46];
#pragma unroll
        for (int i = 0; i < 46; i++) av[i] = s_aw[c][tg * 16 + i];
#pragma unroll
        for (int k = 0; k < KS_; k++) {
            float wv = s_w[(f * 2 + c) * KS_ + k];
#pragma unroll
            for (int tt = 0; tt < 16; tt++) acc[tt] += wv * av[k + tt];
        }
    }
#pragma unroll
    for (int tt = 0; tt < 16; tt++)
        conv_out[(size_t)(b * T_ + t0 + tg * 16 + tt) * F_ + f] = acc[tt];
}

// ---------------- energy: tanh(pq + pm + conv@lfc) . W_v -> energies[b][t] ----------------
__global__ __launch_bounds__(128) void energy_kernel(
    const float* __restrict__ conv_in,  // [b][t][f]
    const float* __restrict__ pm,       // [B,T,A]
    const float* __restrict__ pq,       // [B,A]
    const float* __restrict__ W_lfc,    // [A,F]
    const float* __restrict__ W_v,      // [A]
    float* __restrict__ energies)       // [B,T]
{
    const int b   = blockIdx.y;
    const int t0  = blockIdx.x * 64;
    const int tid = threadIdx.x;
    const int wid = tid >> 5, lane = tid & 31;

    __shared__ float s_cv[64][32];
    __shared__ float s_part[4][64];

    const float4* src = (const float4*)(conv_in + (size_t)(b * T_ + t0) * F_);
#pragma unroll
    for (int r = 0; r < 4; r++)
        ((float4*)s_cv)[tid + r * 128] = src[tid + r * 128];

    float r_lfc[32];
    const float4* lf4 = (const float4*)(W_lfc + tid * F_);
#pragma unroll
    for (int i = 0; i < 8; i++) {
        float4 v = lf4[i];
        r_lfc[i * 4] = v.x; r_lfc[i * 4 + 1] = v.y;
        r_lfc[i * 4 + 2] = v.z; r_lfc[i * 4 + 3] = v.w;
    }
    float r_pq = pq[b * A_ + tid];
    float r_wv = W_v[tid];
    const float* pmb = pm + ((size_t)b * T_ + t0) * A_ + tid;
    __syncthreads();

#pragma unroll 2
    for (int t = 0; t < 64; t++) {
        float la = 0.f;
#pragma unroll
        for (int q = 0; q < 8; q++) {
            float4 cv = *(const float4*)&s_cv[t][q * 4];
            la += cv.x * r_lfc[4 * q]     + cv.y * r_lfc[4 * q + 1]
                + cv.z * r_lfc[4 * q + 2] + cv.w * r_lfc[4 * q + 3];
        }
        float v = fast_tanh(r_pq + pmb[(size_t)t * A_] + la) * r_wv;
#pragma unroll
        for (int o = 16; o; o >>= 1) v += __shfl_xor_sync(0xffffffffu, v, o);
        if (lane == 0) s_part[wid][t] = v;
    }
    __syncthreads();
    if (tid < 64)
        energies[b * T_ + t0 + tid] =
            s_part[0][tid] + s_part[1][tid] + s_part[2][tid] + s_part[3][tid];
}

// ---------------- masked softmax over T (mask int32) ----------------
__global__ __launch_bounds__(256) void softmax_kernel(
    const float* __restrict__ energies, const int* __restrict__ mask,
    float* __restrict__ weights)
{
    int b = blockIdx.x, tid = threadIdx.x;
    __shared__ float red[8];
    __shared__ float s_bcast;
    float v[8];
    float mx = -3.4e38f;
#pragma unroll
    for (int r = 0; r < 8; r++) {
        int t = tid + r * 256;
        float e = energies[b * T_ + t];
        if (mask[b * T_ + t] != 0) e = -1e30f;
        v[r] = e;
        mx = fmaxf(mx, e);
    }
#pragma unroll
    for (int o = 16; o; o >>= 1) mx = fmaxf(mx, __shfl_xor_sync(0xffffffffu, mx, o));
    if ((tid & 31) == 0) red[tid >> 5] = mx;
    __syncthreads();
    if (tid < 8) {
        float m = red[tid];
#pragma unroll
        for (int o = 4; o; o >>= 1) m = fmaxf(m, __shfl_xor_sync(0xffu, m, o));
        if (tid == 0) s_bcast = m;
    }
    __syncthreads();
    mx = s_bcast;
    float sum = 0.f;
#pragma unroll
    for (int r = 0; r < 8; r++) { v[r] = __expf(v[r] - mx); sum += v[r]; }
#pragma unroll
    for (int o = 16; o; o >>= 1) sum += __shfl_xor_sync(0xffffffffu, sum, o);
    if ((tid & 31) == 0) red[tid >> 5] = sum;
    __syncthreads();
    if (tid < 8) {
        float m = red[tid];
#pragma unroll
        for (int o = 4; o; o >>= 1) m += __shfl_xor_sync(0xffu, m, o);
        if (tid == 0) s_bcast = m;
    }
    __syncthreads();
    float inv = 1.f / s_bcast;
#pragma unroll
    for (int r = 0; r < 8; r++) weights[b * T_ + tid + r * 256] = v[r] * inv;
}

// ---------------- context ----------------
__global__ void zero_kernel(float* p)
{
    p[blockIdx.x * blockDim.x + threadIdx.x] = 0.f;
}

__global__ __launch_bounds__(256) void ctx_kernel(
    const float* __restrict__ weights, const float* __restrict__ memory,
    float* __restrict__ ctx)
{
    int b = blockIdx.y;
    int t0 = blockIdx.x * 128;
    int e = threadIdx.x;
    const float* mb = memory + ((size_t)b * T_ + t0) * E_ + e;
    const float* wb = weights + b * T_ + t0;
    float acc = 0.f;
#pragma unroll 4
    for (int t = 0; t < 128; t++) acc += wb[t] * mb[(size_t)t * E_];
    atomicAdd(&ctx[b * E_ + e], acc);
}

// ---------------- stop gate ----------------
__global__ __launch_bounds__(1024) void gate_kernel(
    const float* __restrict__ dh, const float* __restrict__ ctx,
    const float* __restrict__ W_gate, const float* __restrict__ b_gate,
    float* __restrict__ out_stop)
{
    int gtid = blockIdx.x * 1024 + threadIdx.x;
    int r = gtid >> 5, lane = gtid & 31;
    float acc = 0.f;
    const float* xr = dh + (size_t)r * D_;
#pragma unroll 4
    for (int k = lane; k < D_; k += 32) acc += xr[k] * W_gate[k];
    const float* cr = ctx + (size_t)r * E_;
#pragma unroll 4
    for (int k = lane; k < E_; k += 32) acc += cr[k] * W_gate[D_ + k];
#pragma unroll
    for (int o = 16; o; o >>= 1) acc += __shfl_xor_sync(0xffffffffu, acc, o);
    if (lane == 0) out_stop[r] = acc + b_gate[0];
}

// ---------------- launch ----------------
extern "C" void kernel_launch(void* const* d_in, const int* in_sizes, int n_in,
                              void* d_out, int out_size)
{
    const float* last_frame = (const float*)d_in[0];
    const float* att_h      = (const float*)d_in[1];
    const float* att_c      = (const float*)d_in[2];
    const float* att_w      = (const float*)d_in[3];
    const float* att_w_cum  = (const float*)d_in[4];
    const float* att_ctx    = (const float*)d_in[5];
    const float* dec_h      = (const float*)d_in[6];
    const float* dec_c      = (const float*)d_in[7];
    const float* memory     = (const float*)d_in[8];
    const float* pmem       = (const float*)d_in[9];
    const float* W_ih_a     = (const float*)d_in[10];
    const float* W_hh_a     = (const float*)d_in[11];
    const float* b_ih_a     = (const float*)d_in[12];
    const float* b_hh_a     = (const float*)d_in[13];
    const float* W_q        = (const float*)d_in[14];
    const float* W_v        = (const float*)d_in[15];
    const float* W_loc      = (const float*)d_in[16];
    const float* W_lfc      = (const float*)d_in[17];
    const float* W_ih_d     = (const float*)d_in[18];
    const float* W_hh_d     = (const float*)d_in[19];
    const float* b_ih_d     = (const float*)d_in[20];
    const float* b_hh_d     = (const float*)d_in[21];
    const float* W_proj     = (const float*)d_in[22];
    const float* b_proj     = (const float*)d_in[23];
    const float* W_gate     = (const float*)d_in[24];
    const float* b_gate     = (const float*)d_in[25];
    const int*   mask       = (const int*)d_in[26];

    float* out = (float*)d_out;
    float* out_proj = out;                      // [64,256]
    float* out_stop = out + B_ * H_;            // [64,1]
    float* out_w    = out + B_ * H_ + B_;       // [64,2048]

    float *gates, *ah, *ac, *pq, *energies, *ctx, *dh, *dc, *conv;
    cudaGetSymbolAddress((void**)&gates,    g_gates);
    cudaGetSymbolAddress((void**)&ah,       g_ah);
    cudaGetSymbolAddress((void**)&ac,       g_ac);
    cudaGetSymbolAddress((void**)&pq,       g_pq);
    cudaGetSymbolAddress((void**)&energies, g_energies);
    cudaGetSymbolAddress((void**)&ctx,      g_ctx);
    cudaGetSymbolAddress((void**)&dh,       g_dh);
    cudaGetSymbolAddress((void**)&dc,       g_dc);
    cudaGetSymbolAddress((void**)&conv,     g_conv);

    // conv (independent of LSTM) first
    conv_kernel<<<dim3(T_ / 64, B_), 128>>>(att_w, att_w_cum, W_loc, conv);

    // 1) attention LSTM gates (tf32 MMA, pipelined)
    mma_gemm3<<<128, 128>>>(last_frame, W_ih_a,       P_, P_ + E_,
                            att_ctx,    W_ih_a + P_,  E_, P_ + E_,
                            att_h,      W_hh_a,       R_, R_,
                            b_ih_a, b_hh_a, gates, 4 * R_);
    lstm_pointwise<<<(B_ * R_) / 256, 256>>>(gates, att_c, ah, ac, R_);

    // 2) query projection pq = ah @ W_q^T
    mma_gemm3<<<A_ / 32, 128>>>(ah, W_q, R_, R_,
                                nullptr, nullptr, 0, 0,
                                nullptr, nullptr, 0, 0,
                                nullptr, nullptr, pq, A_);

    // 3) energies + softmax
    energy_kernel<<<dim3(T_ / 64, B_), 128>>>(conv, pmem, pq, W_lfc, W_v, energies);
    softmax_kernel<<<B_, 256>>>(energies, mask, out_w);

    // 4) context
    zero_kernel<<<B_, E_>>>(ctx);
    ctx_kernel<<<dim3(16, B_), 256>>>(out_w, memory, ctx);

    // 5) decoder LSTM gates (tf32 MMA, pipelined)
    mma_gemm3<<<128, 128>>>(ah,    W_ih_d,       R_, R_ + E_,
                            ctx,   W_ih_d + R_,  E_, R_ + E_,
                            dec_h, W_hh_d,       D_, D_,
                            b_ih_d, b_hh_d, gates, 4 * D_);
    lstm_pointwise<<<(B_ * D_) / 256, 256>>>(gates, dec_c, dh, dc, D_);

    // 6) output heads
    mma_gemm3<<<H_ / 32, 128>>>(dh,  W_proj,       D_, D_ + E_,
                                ctx, W_proj + D_,  E_, D_ + E_,
                                nullptr, nullptr, 0, 0,
                                b_proj, nullptr, out_proj, H_);
    gate_kernel<<<2, 1024>>>(dh, ctx, W_gate, b_gate, out_stop);
}

// round 8
// speedup vs baseline: 2.3101x; 1.1549x over previous
#include <cuda_runtime.h>

// Problem dims
#define B_  64
#define T_  2048
#define E_  256
#define A_  128
#define P_  128
#define R_  1024
#define D_  1024
#define H_  256
#define F_  32
#define KS_ 31
#define PAD_ 15

// ---------------- scratch (no allocations allowed) ----------------
__device__ float g_gates_a[B_ * 4096];
__device__ float g_gates_d[B_ * 4096];
__device__ float g_ah[B_ * R_];
__device__ float g_ac[B_ * R_];
__device__ float g_pq[B_ * A_];
__device__ float g_energies[B_ * T_];
__device__ float g_ctx[B_ * E_];
__device__ float g_dh[B_ * D_];
__device__ float g_dc[B_ * D_];
__device__ float g_conv[(size_t)B_ * T_ * F_];   // [b][t][f]

// ---------------- helpers ----------------
__device__ __forceinline__ unsigned f2tf(float f) {
    unsigned u;
    asm("cvt.rna.tf32.f32 %0, %1;" : "=r"(u) : "f"(f));
    return u;
}

__device__ __forceinline__ void mma_tf32(float* c,
    unsigned a0, unsigned a1, unsigned a2, unsigned a3,
    unsigned b0, unsigned b1)
{
    asm volatile(
        "mma.sync.aligned.m16n8k8.row.col.f32.tf32.tf32.f32 "
        "{%0,%1,%2,%3}, {%4,%5,%6,%7}, {%8,%9}, {%0,%1,%2,%3};"
        : "+f"(c[0]), "+f"(c[1]), "+f"(c[2]), "+f"(c[3])
        : "r"(a0), "r"(a1), "r"(a2), "r"(a3), "r"(b0), "r"(b1));
}

__device__ __forceinline__ void cp16(void* smem_dst, const void* gsrc) {
    unsigned dst = (unsigned)__cvta_generic_to_shared(smem_dst);
    asm volatile("cp.async.ca.shared.global [%0], [%1], 16;"
                 :: "r"(dst), "l"(gsrc));
}
__device__ __forceinline__ void cp_commit() {
    asm volatile("cp.async.commit_group;");
}
__device__ __forceinline__ void cp_wait1() {
    asm volatile("cp.async.wait_group 1;");
}

__device__ __forceinline__ float sigm(float x) { return 1.f / (1.f + __expf(-x)); }
__device__ __forceinline__ float fast_tanh(float x) {
    float e = __expf(2.f * x);
    return 1.f - __fdividef(2.f, e + 1.f);
}

// ---------------- output init: preload biases / zeros ----------------
__global__ void init_kernel(float* ga, const float* bia, const float* bha,
                            float* gd, const float* bid, const float* bhd,
                            float* pq, float* proj, const float* bp, float* ctx)
{
    int idx = blockIdx.x * blockDim.x + threadIdx.x;   // 0 .. 262143
    int n = idx & 4095;
    ga[idx] = bia[n] + bha[n];
    gd[idx] = bid[n] + bhd[n];
    if (idx < B_ * A_) pq[idx] = 0.f;
    if (idx < B_ * H_) proj[idx] = bp[idx & (H_ - 1)];
    if (idx < B_ * E_) ctx[idx] = 0.f;
}

// ---------------- tf32 MMA 3-segment GEMM, split-K + cp.async pipeline ----------
// C[64,N] += sum_s x_s @ W_s^T (atomic accumulation; C pre-initialized with bias).
// BM=64, BN=32, BK=32, 128 threads. gridDim.y = split count over concatenated K.
__global__ __launch_bounds__(128) void mma_gemm3(
    const float* __restrict__ x1, const float* __restrict__ W1, int K1, int ld1,
    const float* __restrict__ x2, const float* __restrict__ W2, int K2, int ld2,
    const float* __restrict__ x3, const float* __restrict__ W3, int K3, int ld3,
    float* __restrict__ C, int N)
{
    __shared__ float As[3][64][36];
    __shared__ float Ws[3][32][36];

    const int tid  = threadIdx.x;
    const int lane = tid & 31;
    const int w    = tid >> 5;
    const int gid  = lane >> 2;
    const int tig  = lane & 3;
    const int n0   = blockIdx.x * 32;

    const int S      = gridDim.y;
    const int nt_tot = (K1 + K2 + K3) >> 5;
    const int per    = (nt_tot + S - 1) / S;
    const int gt0    = blockIdx.y * per;
    const int gt1    = min(gt0 + per, nt_tot);

    float acc[4][4] = {};

    int base = 0;
#pragma unroll
    for (int s = 0; s < 3; s++) {
        const float* x  = (s == 0) ? x1 : (s == 1) ? x2 : x3;
        const float* W  = (s == 0) ? W1 : (s == 1) ? W2 : W3;
        const int K     = (s == 0) ? K1 : (s == 1) ? K2 : K3;
        const int ld    = (s == 0) ? ld1 : (s == 1) ? ld2 : ld3;
        if (K == 0) continue;
        const int nts = K >> 5;
        const int lo = max(gt0 - base, 0), hi = min(gt1 - base, nts);
        base += nts;
        if (lo >= hi) continue;

        __syncthreads();   // buffers free from previous region

        auto issue = [&](int tile, int buf) {
            int k0 = tile * 32;
#pragma unroll
            for (int r = 0; r < 4; r++) {
                int j = tid + r * 128;
                int m = j >> 3, kq = j & 7;
                cp16(&As[buf][m][kq * 4], x + (size_t)m * K + k0 + kq * 4);
            }
#pragma unroll
            for (int r = 0; r < 2; r++) {
                int j = tid + r * 128;
                int n = j >> 3, kq = j & 7;
                cp16(&Ws[buf][n][kq * 4], W + (size_t)(n0 + n) * ld + k0 + kq * 4);
            }
        };

        issue(lo, 0);
        cp_commit();
        if (hi - lo > 1) issue(lo + 1, 1);
        cp_commit();

        for (int it = lo; it < hi; it++) {
            cp_wait1();
            __syncthreads();
            int nx = it + 2;
            if (nx < hi) issue(nx, (nx - lo) % 3);
            cp_commit();

            const int buf = (it - lo) % 3;
#pragma unroll
            for (int kk = 0; kk < 32; kk += 8) {
                unsigned bb0 = f2tf(Ws[buf][w * 8 + gid][kk + tig]);
                unsigned bb1 = f2tf(Ws[buf][w * 8 + gid][kk + tig + 4]);
#pragma unroll
                for (int mt = 0; mt < 4; mt++) {
                    int ra = mt * 16 + gid;
                    unsigned a0 = f2tf(As[buf][ra][kk + tig]);
                    unsigned a1 = f2tf(As[buf][ra + 8][kk + tig]);
                    unsigned a2 = f2tf(As[buf][ra][kk + tig + 4]);
                    unsigned a3 = f2tf(As[buf][ra + 8][kk + tig + 4]);
                    mma_tf32(acc[mt], a0, a1, a2, a3, bb0, bb1);
                }
            }
        }
    }

    // epilogue: atomic accumulate (C pre-initialized with bias by init_kernel)
    int n = n0 + w * 8 + tig * 2;
#pragma unroll
    for (int mt = 0; mt < 4; mt++) {
        int ra = mt * 16 + gid, rb = ra + 8;
        atomicAdd(&C[(size_t)ra * N + n],     acc[mt][0]);
        atomicAdd(&C[(size_t)ra * N + n + 1], acc[mt][1]);
        atomicAdd(&C[(size_t)rb * N + n],     acc[mt][2]);
        atomicAdd(&C[(size_t)rb * N + n + 1], acc[mt][3]);
    }
}

// ---------------- LSTM pointwise ----------------
__global__ void lstm_pointwise(const float* __restrict__ gates,
                               const float* __restrict__ c_prev,
                               float* __restrict__ h_out, float* __restrict__ c_out,
                               int Nc)
{
    int idx = blockIdx.x * blockDim.x + threadIdx.x;
    if (idx >= B_ * Nc) return;
    int b = idx / Nc, j = idx - b * Nc;
    const float* g = gates + (size_t)b * 4 * Nc;
    float gi = sigm(g[j]);
    float gf = sigm(g[Nc + j]);
    float gg = fast_tanh(g[2 * Nc + j]);
    float go = sigm(g[3 * Nc + j]);
    float c2 = gf * c_prev[idx] + gi * gg;
    h_out[idx] = go * fast_tanh(c2);
    c_out[idx] = c2;
}

// ---------------- conv31 over (att_w, att_w_cum) -> g_conv[b][t][f] ----------------
__global__ __launch_bounds__(128) void conv_kernel(
    const float* __restrict__ att_w, const float* __restrict__ att_w_cum,
    const float* __restrict__ W_loc, float* __restrict__ conv_out)
{
    const int b  = blockIdx.y;
    const int t0 = blockIdx.x * 64;
    const int tid = threadIdx.x;

    __shared__ float s_aw[2][94];
    __shared__ float s_w[F_ * 2 * KS_];

    for (int i = tid; i < 94; i += 128) {
        int g = t0 - PAD_ + i;
        bool ok = (g >= 0) && (g < T_);
        s_aw[0][i] = ok ? att_w[b * T_ + g] : 0.f;
        s_aw[1][i] = ok ? att_w_cum[b * T_ + g] : 0.f;
    }
    for (int i = tid; i < F_ * 2 * KS_; i += 128) s_w[i] = W_loc[i];
    __syncthreads();

    int f = tid & 31, tg = tid >> 5;
    float acc[16];
#pragma unroll
    for (int i = 0; i < 16; i++) acc[i] = 0.f;
#pragma unroll
    for (int c = 0; c < 2; c++) {
        float av[46];
#pragma unroll
        for (int i = 0; i < 46; i++) av[i] = s_aw[c][tg * 16 + i];
#pragma unroll
        for (int k = 0; k < KS_; k++) {
            float wv = s_w[(f * 2 + c) * KS_ + k];
#pragma unroll
            for (int tt = 0; tt < 16; tt++) acc[tt] += wv * av[k + tt];
        }
    }
#pragma unroll
    for (int tt = 0; tt < 16; tt++)
        conv_out[(size_t)(b * T_ + t0 + tg * 16 + tt) * F_ + f] = acc[tt];
}

// ---------------- energy: tanh(pq + pm + conv@lfc) . W_v -> energies[b][t] ----------------
__global__ __launch_bounds__(128) void energy_kernel(
    const float* __restrict__ conv_in,  // [b][t][f]
    const float* __restrict__ pm,       // [B,T,A]
    const float* __restrict__ pq,       // [B,A]
    const float* __restrict__ W_lfc,    // [A,F]
    const float* __restrict__ W_v,      // [A]
    float* __restrict__ energies)       // [B,T]
{
    const int b   = blockIdx.y;
    const int t0  = blockIdx.x * 64;
    const int tid = threadIdx.x;
    const int wid = tid >> 5, lane = tid & 31;

    __shared__ float s_cv[64][32];
    __shared__ float s_part[4][64];

    const float4* src = (const float4*)(conv_in + (size_t)(b * T_ + t0) * F_);
#pragma unroll
    for (int r = 0; r < 4; r++)
        ((float4*)s_cv)[tid + r * 128] = src[tid + r * 128];

    float r_lfc[32];
    const float4* lf4 = (const float4*)(W_lfc + tid * F_);
#pragma unroll
    for (int i = 0; i < 8; i++) {
        float4 v = lf4[i];
        r_lfc[i * 4] = v.x; r_lfc[i * 4 + 1] = v.y;
        r_lfc[i * 4 + 2] = v.z; r_lfc[i * 4 + 3] = v.w;
    }
    float r_pq = pq[b * A_ + tid];
    float r_wv = W_v[tid];
    const float* pmb = pm + ((size_t)b * T_ + t0) * A_ + tid;
    __syncthreads();

#pragma unroll 2
    for (int t = 0; t < 64; t++) {
        float la = 0.f;
#pragma unroll
        for (int q = 0; q < 8; q++) {
            float4 cv = *(const float4*)&s_cv[t][q * 4];
            la += cv.x * r_lfc[4 * q]     + cv.y * r_lfc[4 * q + 1]
                + cv.z * r_lfc[4 * q + 2] + cv.w * r_lfc[4 * q + 3];
        }
        float v = fast_tanh(r_pq + pmb[(size_t)t * A_] + la) * r_wv;
#pragma unroll
        for (int o = 16; o; o >>= 1) v += __shfl_xor_sync(0xffffffffu, v, o);
        if (lane == 0) s_part[wid][t] = v;
    }
    __syncthreads();
    if (tid < 64)
        energies[b * T_ + t0 + tid] =
            s_part[0][tid] + s_part[1][tid] + s_part[2][tid] + s_part[3][tid];
}

// ---------------- masked softmax over T (mask int32) ----------------
__global__ __launch_bounds__(256) void softmax_kernel(
    const float* __restrict__ energies, const int* __restrict__ mask,
    float* __restrict__ weights)
{
    int b = blockIdx.x, tid = threadIdx.x;
    __shared__ float red[8];
    __shared__ float s_bcast;
    float v[8];
    float mx = -3.4e38f;
#pragma unroll
    for (int r = 0; r < 8; r++) {
        int t = tid + r * 256;
        float e = energies[b * T_ + t];
        if (mask[b * T_ + t] != 0) e = -1e30f;
        v[r] = e;
        mx = fmaxf(mx, e);
    }
#pragma unroll
    for (int o = 16; o; o >>= 1) mx = fmaxf(mx, __shfl_xor_sync(0xffffffffu, mx, o));
    if ((tid & 31) == 0) red[tid >> 5] = mx;
    __syncthreads();
    if (tid < 8) {
        float m = red[tid];
#pragma unroll
        for (int o = 4; o; o >>= 1) m = fmaxf(m, __shfl_xor_sync(0xffu, m, o));
        if (tid == 0) s_bcast = m;
    }
    __syncthreads();
    mx = s_bcast;
    float sum = 0.f;
#pragma unroll
    for (int r = 0; r < 8; r++) { v[r] = __expf(v[r] - mx); sum += v[r]; }
#pragma unroll
    for (int o = 16; o; o >>= 1) sum += __shfl_xor_sync(0xffffffffu, sum, o);
    if ((tid & 31) == 0) red[tid >> 5] = sum;
    __syncthreads();
    if (tid < 8) {
        float m = red[tid];
#pragma unroll
        for (int o = 4; o; o >>= 1) m += __shfl_xor_sync(0xffu, m, o);
        if (tid == 0) s_bcast = m;
    }
    __syncthreads();
    float inv = 1.f / s_bcast;
#pragma unroll
    for (int r = 0; r < 8; r++) weights[b * T_ + tid + r * 256] = v[r] * inv;
}

// ---------------- context ----------------
__global__ __launch_bounds__(256) void ctx_kernel(
    const float* __restrict__ weights, const float* __restrict__ memory,
    float* __restrict__ ctx)
{
    int b = blockIdx.y;
    int t0 = blockIdx.x * 128;
    int e = threadIdx.x;
    const float* mb = memory + ((size_t)b * T_ + t0) * E_ + e;
    const float* wb = weights + b * T_ + t0;
    float acc = 0.f;
#pragma unroll 4
    for (int t = 0; t < 128; t++) acc += wb[t] * mb[(size_t)t * E_];
    atomicAdd(&ctx[b * E_ + e], acc);
}

// ---------------- stop gate ----------------
__global__ __launch_bounds__(1024) void gate_kernel(
    const float* __restrict__ dh, const float* __restrict__ ctx,
    const float* __restrict__ W_gate, const float* __restrict__ b_gate,
    float* __restrict__ out_stop)
{
    int gtid = blockIdx.x * 1024 + threadIdx.x;
    int r = gtid >> 5, lane = gtid & 31;
    float acc = 0.f;
    const float* xr = dh + (size_t)r * D_;
#pragma unroll 4
    for (int k = lane; k < D_; k += 32) acc += xr[k] * W_gate[k];
    const float* cr = ctx + (size_t)r * E_;
#pragma unroll 4
    for (int k = lane; k < E_; k += 32) acc += cr[k] * W_gate[D_ + k];
#pragma unroll
    for (int o = 16; o; o >>= 1) acc += __shfl_xor_sync(0xffffffffu, acc, o);
    if (lane == 0) out_stop[r] = acc + b_gate[0];
}

// ---------------- launch ----------------
extern "C" void kernel_launch(void* const* d_in, const int* in_sizes, int n_in,
                              void* d_out, int out_size)
{
    const float* last_frame = (const float*)d_in[0];
    const float* att_h      = (const float*)d_in[1];
    const float* att_c      = (const float*)d_in[2];
    const float* att_w      = (const float*)d_in[3];
    const float* att_w_cum  = (const float*)d_in[4];
    const float* att_ctx    = (const float*)d_in[5];
    const float* dec_h      = (const float*)d_in[6];
    const float* dec_c      = (const float*)d_in[7];
    const float* memory     = (const float*)d_in[8];
    const float* pmem       = (const float*)d_in[9];
    const float* W_ih_a     = (const float*)d_in[10];
    const float* W_hh_a     = (const float*)d_in[11];
    const float* b_ih_a     = (const float*)d_in[12];
    const float* b_hh_a     = (const float*)d_in[13];
    const float* W_q        = (const float*)d_in[14];
    const float* W_v        = (const float*)d_in[15];
    const float* W_loc      = (const float*)d_in[16];
    const float* W_lfc      = (const float*)d_in[17];
    const float* W_ih_d     = (const float*)d_in[18];
    const float* W_hh_d     = (const float*)d_in[19];
    const float* b_ih_d     = (const float*)d_in[20];
    const float* b_hh_d     = (const float*)d_in[21];
    const float* W_proj     = (const float*)d_in[22];
    const float* b_proj     = (const float*)d_in[23];
    const float* W_gate     = (const float*)d_in[24];
    const float* b_gate     = (const float*)d_in[25];
    const int*   mask       = (const int*)d_in[26];

    float* out = (float*)d_out;
    float* out_proj = out;                      // [64,256]
    float* out_stop = out + B_ * H_;            // [64,1]
    float* out_w    = out + B_ * H_ + B_;       // [64,2048]

    float *gates_a, *gates_d, *ah, *ac, *pq, *energies, *ctx, *dh, *dc, *conv;
    cudaGetSymbolAddress((void**)&gates_a,  g_gates_a);
    cudaGetSymbolAddress((void**)&gates_d,  g_gates_d);
    cudaGetSymbolAddress((void**)&ah,       g_ah);
    cudaGetSymbolAddress((void**)&ac,       g_ac);
    cudaGetSymbolAddress((void**)&pq,       g_pq);
    cudaGetSymbolAddress((void**)&energies, g_energies);
    cudaGetSymbolAddress((void**)&ctx,      g_ctx);
    cudaGetSymbolAddress((void**)&dh,       g_dh);
    cudaGetSymbolAddress((void**)&dc,       g_dc);
    cudaGetSymbolAddress((void**)&conv,     g_conv);

    // 0) init outputs with biases / zeros
    init_kernel<<<1024, 256>>>(gates_a, b_ih_a, b_hh_a,
                               gates_d, b_ih_d, b_hh_d,
                               pq, out_proj, b_proj, ctx);

    // conv (independent of LSTM)
    conv_kernel<<<dim3(T_ / 64, B_), 128>>>(att_w, att_w_cum, W_loc, conv);

    // 1) attention LSTM gates (split-K 4: 44 tiles -> 11/block, 512 blocks)
    mma_gemm3<<<dim3(128, 4), 128>>>(last_frame, W_ih_a,       P_, P_ + E_,
                                     att_ctx,    W_ih_a + P_,  E_, P_ + E_,
                                     att_h,      W_hh_a,       R_, R_,
                                     gates_a, 4 * R_);
    lstm_pointwise<<<(B_ * R_) / 256, 256>>>(gates_a, att_c, ah, ac, R_);

    // 2) query projection pq = ah @ W_q^T (split-K 8: 32 tiles -> 4/block)
    mma_gemm3<<<dim3(A_ / 32, 8), 128>>>(ah, W_q, R_, R_,
                                         nullptr, nullptr, 0, 0,
                                         nullptr, nullptr, 0, 0,
                                         pq, A_);

    // 3) energies + softmax
    energy_kernel<<<dim3(T_ / 64, B_), 128>>>(conv, pmem, pq, W_lfc, W_v, energies);
    softmax_kernel<<<B_, 256>>>(energies, mask, out_w);

    // 4) context
    ctx_kernel<<<dim3(16, B_), 256>>>(out_w, memory, ctx);

    // 5) decoder LSTM gates (split-K 8: 72 tiles -> 9/block, 1024 blocks)
    mma_gemm3<<<dim3(128, 8), 128>>>(ah,    W_ih_d,       R_, R_ + E_,
                                     ctx,   W_ih_d + R_,  E_, R_ + E_,
                                     dec_h, W_hh_d,       D_, D_,
                                     gates_d, 4 * D_);
    lstm_pointwise<<<(B_ * D_) / 256, 256>>>(gates_d, dec_c, dh, dc, D_);

    // 6) output heads (proj split-K 8: 40 tiles -> 5/block)
    mma_gemm3<<<dim3(H_ / 32, 8), 128>>>(dh,  W_proj,       D_, D_ + E_,
                                         ctx, W_proj + D_,  E_, D_ + E_,
                                         nullptr, nullptr, 0, 0,
                                         out_proj, H_);
    gate_kernel<<<2, 1024>>>(dh, ctx, W_gate, b_gate, out_stop);
}

// round 11
// speedup vs baseline: 2.4529x; 1.0618x over previous
#include <cuda_runtime.h>

// Problem dims
#define B_  64
#define T_  2048
#define E_  256
#define A_  128
#define P_  128
#define R_  1024
#define D_  1024
#define H_  256
#define F_  32
#define KS_ 31
#define PAD_ 15

// ---------------- scratch (no allocations allowed) ----------------
__device__ float g_gates_a[B_ * 4096];
__device__ float g_gates_d[B_ * 4096];
__device__ float g_ah[B_ * R_];
__device__ float g_ac[B_ * R_];
__device__ float g_pq[B_ * A_];
__device__ float g_energies[B_ * T_];
__device__ float g_ctx[B_ * E_];
__device__ float g_dh[B_ * D_];
__device__ float g_dc[B_ * D_];

// ---------------- helpers ----------------
__device__ __forceinline__ unsigned f2tf(float f) {
    unsigned u;
    asm("cvt.rna.tf32.f32 %0, %1;" : "=r"(u) : "f"(f));
    return u;
}

__device__ __forceinline__ void mma_tf32(float* c,
    unsigned a0, unsigned a1, unsigned a2, unsigned a3,
    unsigned b0, unsigned b1)
{
    asm volatile(
        "mma.sync.aligned.m16n8k8.row.col.f32.tf32.tf32.f32 "
        "{%0,%1,%2,%3}, {%4,%5,%6,%7}, {%8,%9}, {%0,%1,%2,%3};"
        : "+f"(c[0]), "+f"(c[1]), "+f"(c[2]), "+f"(c[3])
        : "r"(a0), "r"(a1), "r"(a2), "r"(a3), "r"(b0), "r"(b1));
}

__device__ __forceinline__ void cp16(void* smem_dst, const void* gsrc) {
    unsigned dst = (unsigned)__cvta_generic_to_shared(smem_dst);
    asm volatile("cp.async.ca.shared.global [%0], [%1], 16;"
                 :: "r"(dst), "l"(gsrc));
}
__device__ __forceinline__ void cp_commit() {
    asm volatile("cp.async.commit_group;");
}
__device__ __forceinline__ void cp_wait1() {
    asm volatile("cp.async.wait_group 1;");
}

__device__ __forceinline__ float sigm(float x) { return 1.f / (1.f + __expf(-x)); }
__device__ __forceinline__ float fast_tanh(float x) {
    float e = __expf(2.f * x);
    return 1.f - __fdividef(2.f, e + 1.f);
}

// ---------------- output init: preload biases / zeros ----------------
__global__ void init_kernel(float* ga, const float* bia, const float* bha,
                            float* gd, const float* bid, const float* bhd,
                            float* pq, float* proj, const float* bp, float* ctx)
{
    int idx = blockIdx.x * blockDim.x + threadIdx.x;   // 0 .. 262143
    int n = idx & 4095;
    ga[idx] = bia[n] + bha[n];
    gd[idx] = bid[n] + bhd[n];
    if (idx < B_ * A_) pq[idx] = 0.f;
    if (idx < B_ * H_) proj[idx] = bp[idx & (H_ - 1)];
    if (idx < B_ * E_) ctx[idx] = 0.f;
}

// ---------------- tf32 MMA 3-segment GEMM, split-K + cp.async pipeline ----------
// C[64,N] += sum_s x_s @ W_s^T (atomic accumulation; C pre-initialized with bias).
// BM=64, BN=32, BK=32, 128 threads. gridDim.y = split count over concatenated K.
__global__ __launch_bounds__(128) void mma_gemm3(
    const float* __restrict__ x1, const float* __restrict__ W1, int K1, int ld1,
    const float* __restrict__ x2, const float* __restrict__ W2, int K2, int ld2,
    const float* __restrict__ x3, const float* __restrict__ W3, int K3, int ld3,
    float* __restrict__ C, int N)
{
    __shared__ float As[3][64][36];
    __shared__ float Ws[3][32][36];

    const int tid  = threadIdx.x;
    const int lane = tid & 31;
    const int w    = tid >> 5;
    const int gid  = lane >> 2;
    const int tig  = lane & 3;
    const int n0   = blockIdx.x * 32;

    const int S      = gridDim.y;
    const int nt_tot = (K1 + K2 + K3) >> 5;
    const int per    = (nt_tot + S - 1) / S;
    const int gt0    = blockIdx.y * per;
    const int gt1    = min(gt0 + per, nt_tot);

    float acc[4][4] = {};

    int base = 0;
#pragma unroll
    for (int s = 0; s < 3; s++) {
        const float* x  = (s == 0) ? x1 : (s == 1) ? x2 : x3;
        const float* W  = (s == 0) ? W1 : (s == 1) ? W2 : W3;
        const int K     = (s == 0) ? K1 : (s == 1) ? K2 : K3;
        const int ld    = (s == 0) ? ld1 : (s == 1) ? ld2 : ld3;
        if (K == 0) continue;
        const int nts = K >> 5;
        const int lo = max(gt0 - base, 0), hi = min(gt1 - base, nts);
        base += nts;
        if (lo >= hi) continue;

        __syncthreads();   // buffers free from previous region

        auto issue = [&](int tile, int buf) {
            int k0 = tile * 32;
#pragma unroll
            for (int r = 0; r < 4; r++) {
                int j = tid + r * 128;
                int m = j >> 3, kq = j & 7;
                cp16(&As[buf][m][kq * 4], x + (size_t)m * K + k0 + kq * 4);
            }
#pragma unroll
            for (int r = 0; r < 2; r++) {
                int j = tid + r * 128;
                int n = j >> 3, kq = j & 7;
                cp16(&Ws[buf][n][kq * 4], W + (size_t)(n0 + n) * ld + k0 + kq * 4);
            }
        };

        issue(lo, 0);
        cp_commit();
        if (hi - lo > 1) issue(lo + 1, 1);
        cp_commit();

        for (int it = lo; it < hi; it++) {
            cp_wait1();
            __syncthreads();
            int nx = it + 2;
            if (nx < hi) issue(nx, (nx - lo) % 3);
            cp_commit();

            const int buf = (it - lo) % 3;
#pragma unroll
            for (int kk = 0; kk < 32; kk += 8) {
                unsigned bb0 = f2tf(Ws[buf][w * 8 + gid][kk + tig]);
                unsigned bb1 = f2tf(Ws[buf][w * 8 + gid][kk + tig + 4]);
#pragma unroll
                for (int mt = 0; mt < 4; mt++) {
                    int ra = mt * 16 + gid;
                    unsigned a0 = f2tf(As[buf][ra][kk + tig]);
                    unsigned a1 = f2tf(As[buf][ra + 8][kk + tig]);
                    unsigned a2 = f2tf(As[buf][ra][kk + tig + 4]);
                    unsigned a3 = f2tf(As[buf][ra + 8][kk + tig + 4]);
                    mma_tf32(acc[mt], a0, a1, a2, a3, bb0, bb1);
                }
            }
        }
    }

    // epilogue: atomic accumulate (C pre-initialized with bias by init_kernel)
    int n = n0 + w * 8 + tig * 2;
#pragma unroll
    for (int mt = 0; mt < 4; mt++) {
        int ra = mt * 16 + gid, rb = ra + 8;
        atomicAdd(&C[(size_t)ra * N + n],     acc[mt][0]);
        atomicAdd(&C[(size_t)ra * N + n + 1], acc[mt][1]);
        atomicAdd(&C[(size_t)rb * N + n],     acc[mt][2]);
        atomicAdd(&C[(size_t)rb * N + n + 1], acc[mt][3]);
    }
}

// ---------------- LSTM pointwise (float4 vectorized) ----------------
__global__ __launch_bounds__(256) void lstm_pointwise(
    const float* __restrict__ gates, const float* __restrict__ c_prev,
    float* __restrict__ h_out, float* __restrict__ c_out, int Nc)
{
    int idx4 = blockIdx.x * blockDim.x + threadIdx.x;   // one float4 each
    if (idx4 >= (B_ * 1024) / 4) return;                // Nc == 1024 here
    int b = idx4 / (Nc / 4), j4 = idx4 - b * (Nc / 4);
    const float4* g = (const float4*)(gates + (size_t)b * 4 * Nc);
    int q = Nc / 4;
    float4 gi4 = g[j4];
    float4 gf4 = g[q + j4];
    float4 gg4 = g[2 * q + j4];
    float4 go4 = g[3 * q + j4];
    float4 cp4 = ((const float4*)c_prev)[idx4];
    float4 h4, c4;
    {
        float c2 = sigm(gf4.x) * cp4.x + sigm(gi4.x) * fast_tanh(gg4.x);
        h4.x = sigm(go4.x) * fast_tanh(c2); c4.x = c2;
    }
    {
        float c2 = sigm(gf4.y) * cp4.y + sigm(gi4.y) * fast_tanh(gg4.y);
        h4.y = sigm(go4.y) * fast_tanh(c2); c4.y = c2;
    }
    {
        float c2 = sigm(gf4.z) * cp4.z + sigm(gi4.z) * fast_tanh(gg4.z);
        h4.z = sigm(go4.z) * fast_tanh(c2); c4.z = c2;
    }
    {
        float c2 = sigm(gf4.w) * cp4.w + sigm(gi4.w) * fast_tanh(gg4.w);
        h4.w = sigm(go4.w) * fast_tanh(c2); c4.w = c2;
    }
    ((float4*)h_out)[idx4] = h4;
    ((float4*)c_out)[idx4] = c4;
}

// ---------------- fused conv31 + location-fc + energy ----------------
// grid (T/64, B), 128 threads. Phase 1: conv into s_cv. Phase 2: la + tanh + reduce.
__global__ __launch_bounds__(128) void energy_kernel(
    const float* __restrict__ att_w, const float* __restrict__ att_w_cum,
    const float* __restrict__ pm,       // [B,T,A]
    const float* __restrict__ pq,       // [B,A]
    const float* __restrict__ W_loc,    // [F,2,31]
    const float* __restrict__ W_lfc,    // [A,F]
    const float* __restrict__ W_v,      // [A]
    float* __restrict__ energies)       // [B,T]
{
    const int b   = blockIdx.y;
    const int t0  = blockIdx.x * 64;
    const int tid = threadIdx.x;
    const int wid = tid >> 5, lane = tid & 31;

    __shared__ float s_aw[2][94];
    __shared__ float s_w[F_ * 2 * KS_];
    __shared__ float s_cv[64][32];      // conv result [t][f]
    __shared__ float s_part[4][64];

    // phase 0: halo + conv weights
    for (int i = tid; i < 94; i += 128) {
        int g = t0 - PAD_ + i;
        bool ok = (g >= 0) && (g < T_);
        s_aw[0][i] = ok ? att_w[b * T_ + g] : 0.f;
        s_aw[1][i] = ok ? att_w_cum[b * T_ + g] : 0.f;
    }
    for (int i = tid; i < F_ * 2 * KS_; i += 128) s_w[i] = W_loc[i];
    __syncthreads();

    // phase 1: conv; thread = (f = tid&31, tg = tid>>5), 16 t's each
    {
        int f = tid & 31, tg = tid >> 5;
        float acc[16];
#pragma unroll
        for (int i = 0; i < 16; i++) acc[i] = 0.f;
#pragma unroll
        for (int c = 0; c < 2; c++) {
            float av[46];
#pragma unroll
            for (int i = 0; i < 46; i++) av[i] = s_aw[c][tg * 16 + i];
#pragma unroll
            for (int k = 0; k < KS_; k++) {
                float wv = s_w[(f * 2 + c) * KS_ + k];
#pragma unroll
                for (int tt = 0; tt < 16; tt++) acc[tt] += wv * av[k + tt];
            }
        }
#pragma unroll
        for (int tt = 0; tt < 16; tt++) s_cv[tg * 16 + tt][f] = acc[tt];
    }

    // phase 2 prep (independent of s_cv)
    float r_lfc[32];
    const float4* lf4 = (const float4*)(W_lfc + tid * F_);
#pragma unroll
    for (int i = 0; i < 8; i++) {
        float4 v = lf4[i];
        r_lfc[i * 4] = v.x; r_lfc[i * 4 + 1] = v.y;
        r_lfc[i * 4 + 2] = v.z; r_lfc[i * 4 + 3] = v.w;
    }
    float r_pq = pq[b * A_ + tid];
    float r_wv = W_v[tid];
    const float* pmb = pm + ((size_t)b * T_ + t0) * A_ + tid;
    __syncthreads();

#pragma unroll 2
    for (int t = 0; t < 64; t++) {
        float la = 0.f;
#pragma unroll
        for (int q = 0; q < 8; q++) {
            float4 cv = *(const float4*)&s_cv[t][q * 4];
            la += cv.x * r_lfc[4 * q]     + cv.y * r_lfc[4 * q + 1]
                + cv.z * r_lfc[4 * q + 2] + cv.w * r_lfc[4 * q + 3];
        }
        float v = fast_tanh(r_pq + pmb[(size_t)t * A_] + la) * r_wv;
#pragma unroll
        for (int o = 16; o; o >>= 1) v += __shfl_xor_sync(0xffffffffu, v, o);
        if (lane == 0) s_part[wid][t] = v;
    }
    __syncthreads();
    if (tid < 64)
        energies[b * T_ + t0 + tid] =
            s_part[0][tid] + s_part[1][tid] + s_part[2][tid] + s_part[3][tid];
}

// ---------------- masked softmax over T (mask int32) ----------------
__global__ __launch_bounds__(256) void softmax_kernel(
    const float* __restrict__ energies, const int* __restrict__ mask,
    float* __restrict__ weights)
{
    int b = blockIdx.x, tid = threadIdx.x;
    __shared__ float red[8];
    __shared__ float s_bcast;
    float v[8];
    float mx = -3.4e38f;
#pragma unroll
    for (int r = 0; r < 8; r++) {
        int t = tid + r * 256;
        float e = energies[b * T_ + t];
        if (mask[b * T_ + t] != 0) e = -1e30f;
        v[r] = e;
        mx = fmaxf(mx, e);
    }
#pragma unroll
    for (int o = 16; o; o >>= 1) mx = fmaxf(mx, __shfl_xor_sync(0xffffffffu, mx, o));
    if ((tid & 31) == 0) red[tid >> 5] = mx;
    __syncthreads();
    if (tid < 8) {
        float m = red[tid];
#pragma unroll
        for (int o = 4; o; o >>= 1) m = fmaxf(m, __shfl_xor_sync(0xffu, m, o));
        if (tid == 0) s_bcast = m;
    }
    __syncthreads();
    mx = s_bcast;
    float sum = 0.f;
#pragma unroll
    for (int r = 0; r < 8; r++) { v[r] = __expf(v[r] - mx); sum += v[r]; }
#pragma unroll
    for (int o = 16; o; o >>= 1) sum += __shfl_xor_sync(0xffffffffu, sum, o);
    if ((tid & 31) == 0) red[tid >> 5] = sum;
    __syncthreads();
    if (tid < 8) {
        float m = red[tid];
#pragma unroll
        for (int o = 4; o; o >>= 1) m += __shfl_xor_sync(0xffu, m, o);
        if (tid == 0) s_bcast = m;
    }
    __syncthreads();
    float inv = 1.f / s_bcast;
#pragma unroll
    for (int r = 0; r < 8; r++) weights[b * T_ + tid + r * 256] = v[r] * inv;
}

// ---------------- context ----------------
__global__ __launch_bounds__(256) void ctx_kernel(
    const float* __restrict__ weights, const float* __restrict__ memory,
    float* __restrict__ ctx)
{
    int b = blockIdx.y;
    int t0 = blockIdx.x * 128;
    int e = threadIdx.x;
    const float* mb = memory + ((size_t)b * T_ + t0) * E_ + e;
    const float* wb = weights + b * T_ + t0;
    float acc = 0.f;
#pragma unroll 4
    for (int t = 0; t < 128; t++) acc += wb[t] * mb[(size_t)t * E_];
    atomicAdd(&ctx[b * E_ + e], acc);
}

// ---------------- stop gate ----------------
__global__ __launch_bounds__(1024) void gate_kernel(
    const float* __restrict__ dh, const float* __restrict__ ctx,
    const float* __restrict__ W_gate, const float* __restrict__ b_gate,
    float* __restrict__ out_stop)
{
    int gtid = blockIdx.x * 1024 + threadIdx.x;
    int r = gtid >> 5, lane = gtid & 31;
    float acc = 0.f;
    const float* xr = dh + (size_t)r * D_;
#pragma unroll 4
    for (int k = lane; k < D_; k += 32) acc += xr[k] * W_gate[k];
    const float* cr = ctx + (size_t)r * E_;
#pragma unroll 4
    for (int k = lane; k < E_; k += 32) acc += cr[k] * W_gate[D_ + k];
#pragma unroll
    for (int o = 16; o; o >>= 1) acc += __shfl_xor_sync(0xffffffffu, acc, o);
    if (lane == 0) out_stop[r] = acc + b_gate[0];
}

// ---------------- launch ----------------
extern "C" void kernel_launch(void* const* d_in, const int* in_sizes, int n_in,
                              void* d_out, int out_size)
{
    const float* last_frame = (const float*)d_in[0];
    const float* att_h      = (const float*)d_in[1];
    const float* att_c      = (const float*)d_in[2];
    const float* att_w      = (const float*)d_in[3];
    const float* att_w_cum  = (const float*)d_in[4];
    const float* att_ctx    = (const float*)d_in[5];
    const float* dec_h      = (const float*)d_in[6];
    const float* dec_c      = (const float*)d_in[7];
    const float* memory     = (const float*)d_in[8];
    const float* pmem       = (const float*)d_in[9];
    const float* W_ih_a     = (const float*)d_in[10];
    const float* W_hh_a     = (const float*)d_in[11];
    const float* b_ih_a     = (const float*)d_in[12];
    const float* b_hh_a     = (const float*)d_in[13];
    const float* W_q        = (const float*)d_in[14];
    const float* W_v        = (const float*)d_in[15];
    const float* W_loc      = (const float*)d_in[16];
    const float* W_lfc      = (const float*)d_in[17];
    const float* W_ih_d     = (const float*)d_in[18];
    const float* W_hh_d     = (const float*)d_in[19];
    const float* b_ih_d     = (const float*)d_in[20];
    const float* b_hh_d     = (const float*)d_in[21];
    const float* W_proj     = (const float*)d_in[22];
    const float* b_proj     = (const float*)d_in[23];
    const float* W_gate     = (const float*)d_in[24];
    const float* b_gate     = (const float*)d_in[25];
    const int*   mask       = (const int*)d_in[26];

    float* out = (float*)d_out;
    float* out_proj = out;                      // [64,256]
    float* out_stop = out + B_ * H_;            // [64,1]
    float* out_w    = out + B_ * H_ + B_;       // [64,2048]

    float *gates_a, *gates_d, *ah, *ac, *pq, *energies, *ctx, *dh, *dc;
    cudaGetSymbolAddress((void**)&gates_a,  g_gates_a);
    cudaGetSymbolAddress((void**)&gates_d,  g_gates_d);
    cudaGetSymbolAddress((void**)&ah,       g_ah);
    cudaGetSymbolAddress((void**)&ac,       g_ac);
    cudaGetSymbolAddress((void**)&pq,       g_pq);
    cudaGetSymbolAddress((void**)&energies, g_energies);
    cudaGetSymbolAddress((void**)&ctx,      g_ctx);
    cudaGetSymbolAddress((void**)&dh,       g_dh);
    cudaGetSymbolAddress((void**)&dc,       g_dc);

    // 0) init outputs with biases / zeros
    init_kernel<<<1024, 256>>>(gates_a, b_ih_a, b_hh_a,
                               gates_d, b_ih_d, b_hh_d,
                               pq, out_proj, b_proj, ctx);

    // 1) attention LSTM gates (split-K 8: 44 tiles -> 6/block)
    mma_gemm3<<<dim3(128, 8), 128>>>(last_frame, W_ih_a,       P_, P_ + E_,
                                     att_ctx,    W_ih_a + P_,  E_, P_ + E_,
                                     att_h,      W_hh_a,       R_, R_,
                                     gates_a, 4 * R_);
    lstm_pointwise<<<(B_ * R_) / 1024, 256>>>(gates_a, att_c, ah, ac, R_);

    // 2) query projection pq = ah @ W_q^T (split-K 8: 4 tiles/block)
    mma_gemm3<<<dim3(A_ / 32, 8), 128>>>(ah, W_q, R_, R_,
                                         nullptr, nullptr, 0, 0,
                                         nullptr, nullptr, 0, 0,
                                         pq, A_);

    // 3) fused conv+energies, then softmax
    energy_kernel<<<dim3(T_ / 64, B_), 128>>>(att_w, att_w_cum, pmem, pq,
                                              W_loc, W_lfc, W_v, energies);
    softmax_kernel<<<B_, 256>>>(energies, mask, out_w);

    // 4) context
    ctx_kernel<<<dim3(16, B_), 256>>>(out_w, memory, ctx);

    // 5) decoder LSTM gates (split-K 16: 72 tiles -> 5/block)
    mma_gemm3<<<dim3(128, 16), 128>>>(ah,    W_ih_d,       R_, R_ + E_,
                                      ctx,   W_ih_d + R_,  E_, R_ + E_,
                                      dec_h, W_hh_d,       D_, D_,
                                      gates_d, 4 * D_);
    lstm_pointwise<<<(B_ * D_) / 1024, 256>>>(gates_d, dec_c, dh, dc, D_);

    // 6) output heads (proj split-K 8: 5 tiles/block)
    mma_gemm3<<<dim3(H_ / 32, 8), 128>>>(dh,  W_proj,       D_, D_ + E_,
                                         ctx, W_proj + D_,  E_, D_ + E_,
                                         nullptr, nullptr, 0, 0,
                                         out_proj, H_);
    gate_kernel<<<2, 1024>>>(dh, ctx, W_gate, b_gate, out_stop);
}

// round 12
// speedup vs baseline: 2.7639x; 1.1268x over previous
#include <cuda_runtime.h>

// Problem dims
#define B_  64
#define T_  2048
#define E_  256
#define A_  128
#define P_  128
#define R_  1024
#define D_  1024
#define H_  256
#define F_  32
#define KS_ 31
#define PAD_ 15

// ---------------- scratch (no allocations allowed) ----------------
__device__ float g_gates_a[B_ * 4096];
__device__ float g_gates_d[B_ * 4096];
__device__ float g_ah[B_ * R_];
__device__ float g_ac[B_ * R_];
__device__ float g_pq[B_ * A_];
__device__ float g_energies[B_ * T_];
__device__ float g_ctx[B_ * E_];
__device__ float g_dh[B_ * D_];
__device__ float g_dc[B_ * D_];

// ---------------- helpers ----------------
__device__ __forceinline__ unsigned f2tf(float f) {
    unsigned u;
    asm("cvt.rna.tf32.f32 %0, %1;" : "=r"(u) : "f"(f));
    return u;
}

__device__ __forceinline__ void mma_tf32(float* c,
    unsigned a0, unsigned a1, unsigned a2, unsigned a3,
    unsigned b0, unsigned b1)
{
    asm volatile(
        "mma.sync.aligned.m16n8k8.row.col.f32.tf32.tf32.f32 "
        "{%0,%1,%2,%3}, {%4,%5,%6,%7}, {%8,%9}, {%0,%1,%2,%3};"
        : "+f"(c[0]), "+f"(c[1]), "+f"(c[2]), "+f"(c[3])
        : "r"(a0), "r"(a1), "r"(a2), "r"(a3), "r"(b0), "r"(b1));
}

__device__ __forceinline__ void cp16(void* smem_dst, const void* gsrc) {
    unsigned dst = (unsigned)__cvta_generic_to_shared(smem_dst);
    asm volatile("cp.async.ca.shared.global [%0], [%1], 16;"
                 :: "r"(dst), "l"(gsrc));
}
__device__ __forceinline__ void cp_commit() {
    asm volatile("cp.async.commit_group;");
}
__device__ __forceinline__ void cp_wait1() {
    asm volatile("cp.async.wait_group 1;");
}
__device__ __forceinline__ void cp_wait0() {
    asm volatile("cp.async.wait_group 0;");
}

__device__ __forceinline__ float sigm(float x) { return 1.f / (1.f + __expf(-x)); }
__device__ __forceinline__ float fast_tanh(float x) {
    float e = __expf(2.f * x);
    return 1.f - __fdividef(2.f, e + 1.f);
}

// ---------------- output init: preload biases / zeros ----------------
__global__ void init_kernel(float* ga, const float* bia, const float* bha,
                            float* gd, const float* bid, const float* bhd,
                            float* pq, float* proj, const float* bp, float* ctx)
{
    int idx = blockIdx.x * blockDim.x + threadIdx.x;   // 0 .. 262143
    int n = idx & 4095;
    ga[idx] = bia[n] + bha[n];
    gd[idx] = bid[n] + bhd[n];
    if (idx < B_ * A_) pq[idx] = 0.f;
    if (idx < B_ * H_) proj[idx] = bp[idx & (H_ - 1)];
    if (idx < B_ * E_) ctx[idx] = 0.f;
}

// ---------------- tf32 MMA 3-segment GEMM, split-K + cp.async pipeline ----------
__global__ __launch_bounds__(128) void mma_gemm3(
    const float* __restrict__ x1, const float* __restrict__ W1, int K1, int ld1,
    const float* __restrict__ x2, const float* __restrict__ W2, int K2, int ld2,
    const float* __restrict__ x3, const float* __restrict__ W3, int K3, int ld3,
    float* __restrict__ C, int N)
{
    __shared__ float As[3][64][36];
    __shared__ float Ws[3][32][36];

    const int tid  = threadIdx.x;
    const int lane = tid & 31;
    const int w    = tid >> 5;
    const int gid  = lane >> 2;
    const int tig  = lane & 3;
    const int n0   = blockIdx.x * 32;

    const int S      = gridDim.y;
    const int nt_tot = (K1 + K2 + K3) >> 5;
    const int per    = (nt_tot + S - 1) / S;
    const int gt0    = blockIdx.y * per;
    const int gt1    = min(gt0 + per, nt_tot);

    float acc[4][4] = {};

    int base = 0;
#pragma unroll
    for (int s = 0; s < 3; s++) {
        const float* x  = (s == 0) ? x1 : (s == 1) ? x2 : x3;
        const float* W  = (s == 0) ? W1 : (s == 1) ? W2 : W3;
        const int K     = (s == 0) ? K1 : (s == 1) ? K2 : K3;
        const int ld    = (s == 0) ? ld1 : (s == 1) ? ld2 : ld3;
        if (K == 0) continue;
        const int nts = K >> 5;
        const int lo = max(gt0 - base, 0), hi = min(gt1 - base, nts);
        base += nts;
        if (lo >= hi) continue;

        __syncthreads();

        auto issue = [&](int tile, int buf) {
            int k0 = tile * 32;
#pragma unroll
            for (int r = 0; r < 4; r++) {
                int j = tid + r * 128;
                int m = j >> 3, kq = j & 7;
                cp16(&As[buf][m][kq * 4], x + (size_t)m * K + k0 + kq * 4);
            }
#pragma unroll
            for (int r = 0; r < 2; r++) {
                int j = tid + r * 128;
                int n = j >> 3, kq = j & 7;
                cp16(&Ws[buf][n][kq * 4], W + (size_t)(n0 + n) * ld + k0 + kq * 4);
            }
        };

        issue(lo, 0);
        cp_commit();
        if (hi - lo > 1) issue(lo + 1, 1);
        cp_commit();

        for (int it = lo; it < hi; it++) {
            cp_wait1();
            __syncthreads();
            int nx = it + 2;
            if (nx < hi) issue(nx, (nx - lo) % 3);
            cp_commit();

            const int buf = (it - lo) % 3;
#pragma unroll
            for (int kk = 0; kk < 32; kk += 8) {
                unsigned bb0 = f2tf(Ws[buf][w * 8 + gid][kk + tig]);
                unsigned bb1 = f2tf(Ws[buf][w * 8 + gid][kk + tig + 4]);
#pragma unroll
                for (int mt = 0; mt < 4; mt++) {
                    int ra = mt * 16 + gid;
                    unsigned a0 = f2tf(As[buf][ra][kk + tig]);
                    unsigned a1 = f2tf(As[buf][ra + 8][kk + tig]);
                    unsigned a2 = f2tf(As[buf][ra][kk + tig + 4]);
                    unsigned a3 = f2tf(As[buf][ra + 8][kk + tig + 4]);
                    mma_tf32(acc[mt], a0, a1, a2, a3, bb0, bb1);
                }
            }
        }
    }

    int n = n0 + w * 8 + tig * 2;
#pragma unroll
    for (int mt = 0; mt < 4; mt++) {
        int ra = mt * 16 + gid, rb = ra + 8;
        atomicAdd(&C[(size_t)ra * N + n],     acc[mt][0]);
        atomicAdd(&C[(size_t)ra * N + n + 1], acc[mt][1]);
        atomicAdd(&C[(size_t)rb * N + n],     acc[mt][2]);
        atomicAdd(&C[(size_t)rb * N + n + 1], acc[mt][3]);
    }
}

// ---------------- LSTM pointwise (float4 vectorized) ----------------
__global__ __launch_bounds__(256) void lstm_pointwise(
    const float* __restrict__ gates, const float* __restrict__ c_prev,
    float* __restrict__ h_out, float* __restrict__ c_out, int Nc)
{
    int idx4 = blockIdx.x * blockDim.x + threadIdx.x;
    if (idx4 >= (B_ * 1024) / 4) return;
    int b = idx4 / (Nc / 4), j4 = idx4 - b * (Nc / 4);
    const float4* g = (const float4*)(gates + (size_t)b * 4 * Nc);
    int q = Nc / 4;
    float4 gi4 = g[j4];
    float4 gf4 = g[q + j4];
    float4 gg4 = g[2 * q + j4];
    float4 go4 = g[3 * q + j4];
    float4 cp4 = ((const float4*)c_prev)[idx4];
    float4 h4, c4;
    { float c2 = sigm(gf4.x) * cp4.x + sigm(gi4.x) * fast_tanh(gg4.x);
      h4.x = sigm(go4.x) * fast_tanh(c2); c4.x = c2; }
    { float c2 = sigm(gf4.y) * cp4.y + sigm(gi4.y) * fast_tanh(gg4.y);
      h4.y = sigm(go4.y) * fast_tanh(c2); c4.y = c2; }
    { float c2 = sigm(gf4.z) * cp4.z + sigm(gi4.z) * fast_tanh(gg4.z);
      h4.z = sigm(go4.z) * fast_tanh(c2); c4.z = c2; }
    { float c2 = sigm(gf4.w) * cp4.w + sigm(gi4.w) * fast_tanh(gg4.w);
      h4.w = sigm(go4.w) * fast_tanh(c2); c4.w = c2; }
    ((float4*)h_out)[idx4] = h4;
    ((float4*)c_out)[idx4] = c4;
}

// ---------------- fused conv31 + MMA location-fc + energy ----------------
// grid (T/64, B), 128 threads, dynamic smem.
// Phase 1: conv -> s_cv. Phase 2: MMA la = s_cv @ W_lfc^T -> s_la.
// Phase 3: per-thread (t, a-half) tanh-dot from smem, cross-half combine.
// smem float offsets:
//   s_pm   0      [64][132]  (pm tile, padded rows: conflict-free lane=t LDS.128)
//   s_la   8448   [64][132]
//   s_lfc  16896  [128][36]
//   s_cv   21504  [64][36]
//   s_w    23808  [1984]
//   s_aw   25792  [2*94] (192 reserved)
//   s_pq   25984  [128]
//   s_wv   26112  [128]
//   s_half 26240  [128]
#define ENERGY_SMEM_FLOATS 26368
__global__ __launch_bounds__(128) void energy_kernel(
    const float* __restrict__ att_w, const float* __restrict__ att_w_cum,
    const float* __restrict__ pm,       // [B,T,A]
    const float* __restrict__ pq,       // [B,A]
    const float* __restrict__ W_loc,    // [F,2,31]
    const float* __restrict__ W_lfc,    // [A,F]
    const float* __restrict__ W_v,      // [A]
    float* __restrict__ energies)       // [B,T]
{
    extern __shared__ float sm[];
    float* s_pm   = sm;
    float* s_la   = sm + 8448;
    float* s_lfc  = sm + 16896;
    float* s_cv   = sm + 21504;
    float* s_w    = sm + 23808;
    float* s_aw   = sm + 25792;
    float* s_pq   = sm + 25984;
    float* s_wv   = sm + 26112;
    float* s_half = sm + 26240;

    const int b   = blockIdx.y;
    const int t0  = blockIdx.x * 64;
    const int tid = threadIdx.x;
    const int lane = tid & 31, w = tid >> 5;
    const int gid = lane >> 2, tig = lane & 3;

    // -- issue all cp.async up front (overlaps with conv phase) --
    const float* pmrow = pm + ((size_t)b * T_ + t0) * A_;
#pragma unroll
    for (int r = 0; r < 16; r++) {
        int idx = tid + r * 128;            // 2048 chunks: pm tile 64x128
        int row = idx >> 5, q = idx & 31;
        cp16(s_pm + row * 132 + q * 4, pmrow + row * 128 + q * 4);
    }
#pragma unroll
    for (int r = 0; r < 8; r++) {
        int idx = tid + r * 128;            // 1024 chunks: lfc 128x32
        int row = idx >> 3, q = idx & 7;
        cp16(s_lfc + row * 36 + q * 4, W_lfc + row * 32 + q * 4);
    }
    if (tid < 32)      cp16(s_pq + tid * 4, pq + b * A_ + tid * 4);
    else if (tid < 64) cp16(s_wv + (tid - 32) * 4, W_v + (tid - 32) * 4);
    cp_commit();

    // -- halo + conv weights (regular loads) --
    for (int i = tid; i < 94; i += 128) {
        int g = t0 - PAD_ + i;
        bool ok = (g >= 0) && (g < T_);
        s_aw[i]      = ok ? att_w[b * T_ + g] : 0.f;
        s_aw[94 + i] = ok ? att_w_cum[b * T_ + g] : 0.f;
    }
    for (int i = tid; i < F_ * 2 * KS_; i += 128) s_w[i] = W_loc[i];
    __syncthreads();

    // -- phase 1: conv; thread = (f = tid&31, tg = tid>>5), 16 t's each --
    {
        int f = tid & 31, tg = tid >> 5;
        float acc[16];
#pragma unroll
        for (int i = 0; i < 16; i++) acc[i] = 0.f;
#pragma unroll
        for (int c = 0; c < 2; c++) {
            float av[46];
#pragma unroll
            for (int i = 0; i < 46; i++) av[i] = s_aw[c * 94 + tg * 16 + i];
#pragma unroll
            for (int k = 0; k < KS_; k++) {
                float wv = s_w[(f * 2 + c) * KS_ + k];
#pragma unroll
                for (int tt = 0; tt < 16; tt++) acc[tt] += wv * av[k + tt];
            }
        }
#pragma unroll
        for (int tt = 0; tt < 16; tt++) s_cv[(tg * 16 + tt) * 36 + f] = acc[tt];
    }
    cp_wait0();
    __syncthreads();

    // -- phase 2: la[64][128] = s_cv[64x32] @ s_lfc[128x32]^T (tf32 MMA) --
    {
        float acc[4][4][4] = {};   // [mt][nt][c]
#pragma unroll
        for (int kk = 0; kk < 32; kk += 8) {
            unsigned af[4][4];
#pragma unroll
            for (int mt = 0; mt < 4; mt++) {
                int ra = mt * 16 + gid;
                af[mt][0] = f2tf(s_cv[ra * 36 + kk + tig]);
                af[mt][1] = f2tf(s_cv[(ra + 8) * 36 + kk + tig]);
                af[mt][2] = f2tf(s_cv[ra * 36 + kk + tig + 4]);
                af[mt][3] = f2tf(s_cv[(ra + 8) * 36 + kk + tig + 4]);
            }
#pragma unroll
            for (int nt = 0; nt < 4; nt++) {
                int n = w * 32 + nt * 8 + gid;
                unsigned bb0 = f2tf(s_lfc[n * 36 + kk + tig]);
                unsigned bb1 = f2tf(s_lfc[n * 36 + kk + tig + 4]);
#pragma unroll
                for (int mt = 0; mt < 4; mt++)
                    mma_tf32(acc[mt][nt], af[mt][0], af[mt][1], af[mt][2], af[mt][3],
                             bb0, bb1);
            }
        }
#pragma unroll
        for (int mt = 0; mt < 4; mt++) {
#pragma unroll
            for (int nt = 0; nt < 4; nt++) {
                int col = w * 32 + nt * 8 + tig * 2;
                int r0 = mt * 16 + gid;
                s_la[r0 * 132 + col]           = acc[mt][nt][0];
                s_la[r0 * 132 + col + 1]       = acc[mt][nt][1];
                s_la[(r0 + 8) * 132 + col]     = acc[mt][nt][2];
                s_la[(r0 + 8) * 132 + col + 1] = acc[mt][nt][3];
            }
        }
    }
    __syncthreads();

    // -- phase 3: thread = (t = tid&63, half = tid>>6); 64 a's each --
    {
        int t = tid & 63, half = tid >> 6;
        const float* pmr = s_pm + t * 132 + half * 64;
        const float* lar = s_la + t * 132 + half * 64;
        const float* pqr = s_pq + half * 64;
        const float* wvr = s_wv + half * 64;
        float accE = 0.f;
#pragma unroll
        for (int i = 0; i < 16; i++) {
            float4 pv = *(const float4*)(pmr + i * 4);
            float4 lv = *(const float4*)(lar + i * 4);
            float4 qv = *(const float4*)(pqr + i * 4);
            float4 wv = *(const float4*)(wvr + i * 4);
            accE += fast_tanh(qv.x + pv.x + lv.x) * wv.x;
            accE += fast_tanh(qv.y + pv.y + lv.y) * wv.y;
            accE += fast_tanh(qv.z + pv.z + lv.z) * wv.z;
            accE += fast_tanh(qv.w + pv.w + lv.w) * wv.w;
        }
        s_half[half * 64 + t] = accE;
    }
    __syncthreads();
    if (tid < 64)
        energies[b * T_ + t0 + tid] = s_half[tid] + s_half[64 + tid];
}

// ---------------- masked softmax over T (mask int32) ----------------
__global__ __launch_bounds__(256) void softmax_kernel(
    const float* __restrict__ energies, const int* __restrict__ mask,
    float* __restrict__ weights)
{
    int b = blockIdx.x, tid = threadIdx.x;
    __shared__ float red[8];
    __shared__ float s_bcast;
    float v[8];
    float mx = -3.4e38f;
#pragma unroll
    for (int r = 0; r < 8; r++) {
        int t = tid + r * 256;
        float e = energies[b * T_ + t];
        if (mask[b * T_ + t] != 0) e = -1e30f;
        v[r] = e;
        mx = fmaxf(mx, e);
    }
#pragma unroll
    for (int o = 16; o; o >>= 1) mx = fmaxf(mx, __shfl_xor_sync(0xffffffffu, mx, o));
    if ((tid & 31) == 0) red[tid >> 5] = mx;
    __syncthreads();
    if (tid < 8) {
        float m = red[tid];
#pragma unroll
        for (int o = 4; o; o >>= 1) m = fmaxf(m, __shfl_xor_sync(0xffu, m, o));
        if (tid == 0) s_bcast = m;
    }
    __syncthreads();
    mx = s_bcast;
    float sum = 0.f;
#pragma unroll
    for (int r = 0; r < 8; r++) { v[r] = __expf(v[r] - mx); sum += v[r]; }
#pragma unroll
    for (int o = 16; o; o >>= 1) sum += __shfl_xor_sync(0xffffffffu, sum, o);
    if ((tid & 31) == 0) red[tid >> 5] = sum;
    __syncthreads();
    if (tid < 8) {
        float m = red[tid];
#pragma unroll
        for (int o = 4; o; o >>= 1) m += __shfl_xor_sync(0xffu, m, o);
        if (tid == 0) s_bcast = m;
    }
    __syncthreads();
    float inv = 1.f / s_bcast;
#pragma unroll
    for (int r = 0; r < 8; r++) weights[b * T_ + tid + r * 256] = v[r] * inv;
}

// ---------------- context ----------------
__global__ __launch_bounds__(256) void ctx_kernel(
    const float* __restrict__ weights, const float* __restrict__ memory,
    float* __restrict__ ctx)
{
    int b = blockIdx.y;
    int t0 = blockIdx.x * 128;
    int e = threadIdx.x;
    const float* mb = memory + ((size_t)b * T_ + t0) * E_ + e;
    const float* wb = weights + b * T_ + t0;
    float acc = 0.f;
#pragma unroll 4
    for (int t = 0; t < 128; t++) acc += wb[t] * mb[(size_t)t * E_];
    atomicAdd(&ctx[b * E_ + e], acc);
}

// ---------------- stop gate ----------------
__global__ __launch_bounds__(1024) void gate_kernel(
    const float* __restrict__ dh, const float* __restrict__ ctx,
    const float* __restrict__ W_gate, const float* __restrict__ b_gate,
    float* __restrict__ out_stop)
{
    int gtid = blockIdx.x * 1024 + threadIdx.x;
    int r = gtid >> 5, lane = gtid & 31;
    float acc = 0.f;
    const float* xr = dh + (size_t)r * D_;
#pragma unroll 4
    for (int k = lane; k < D_; k += 32) acc += xr[k] * W_gate[k];
    const float* cr = ctx + (size_t)r * E_;
#pragma unroll 4
    for (int k = lane; k < E_; k += 32) acc += cr[k] * W_gate[D_ + k];
#pragma unroll
    for (int o = 16; o; o >>= 1) acc += __shfl_xor_sync(0xffffffffu, acc, o);
    if (lane == 0) out_stop[r] = acc + b_gate[0];
}

// ---------------- launch ----------------
extern "C" void kernel_launch(void* const* d_in, const int* in_sizes, int n_in,
                              void* d_out, int out_size)
{
    const float* last_frame = (const float*)d_in[0];
    const float* att_h      = (const float*)d_in[1];
    const float* att_c      = (const float*)d_in[2];
    const float* att_w      = (const float*)d_in[3];
    const float* att_w_cum  = (const float*)d_in[4];
    const float* att_ctx    = (const float*)d_in[5];
    const float* dec_h      = (const float*)d_in[6];
    const float* dec_c      = (const float*)d_in[7];
    const float* memory     = (const float*)d_in[8];
    const float* pmem       = (const float*)d_in[9];
    const float* W_ih_a     = (const float*)d_in[10];
    const float* W_hh_a     = (const float*)d_in[11];
    const float* b_ih_a     = (const float*)d_in[12];
    const float* b_hh_a     = (const float*)d_in[13];
    const float* W_q        = (const float*)d_in[14];
    const float* W_v        = (const float*)d_in[15];
    const float* W_loc      = (const float*)d_in[16];
    const float* W_lfc      = (const float*)d_in[17];
    const float* W_ih_d     = (const float*)d_in[18];
    const float* W_hh_d     = (const float*)d_in[19];
    const float* b_ih_d     = (const float*)d_in[20];
    const float* b_hh_d     = (const float*)d_in[21];
    const float* W_proj     = (const float*)d_in[22];
    const float* b_proj     = (const float*)d_in[23];
    const float* W_gate     = (const float*)d_in[24];
    const float* b_gate     = (const float*)d_in[25];
    const int*   mask       = (const int*)d_in[26];

    float* out = (float*)d_out;
    float* out_proj = out;                      // [64,256]
    float* out_stop = out + B_ * H_;            // [64,1]
    float* out_w    = out + B_ * H_ + B_;       // [64,2048]

    float *gates_a, *gates_d, *ah, *ac, *pq, *energies, *ctx, *dh, *dc;
    cudaGetSymbolAddress((void**)&gates_a,  g_gates_a);
    cudaGetSymbolAddress((void**)&gates_d,  g_gates_d);
    cudaGetSymbolAddress((void**)&ah,       g_ah);
    cudaGetSymbolAddress((void**)&ac,       g_ac);
    cudaGetSymbolAddress((void**)&pq,       g_pq);
    cudaGetSymbolAddress((void**)&energies, g_energies);
    cudaGetSymbolAddress((void**)&ctx,      g_ctx);
    cudaGetSymbolAddress((void**)&dh,       g_dh);
    cudaGetSymbolAddress((void**)&dc,       g_dc);

    const int energy_smem = ENERGY_SMEM_FLOATS * 4;   // 105,472 B
    cudaFuncSetAttribute(energy_kernel,
                         cudaFuncAttributeMaxDynamicSharedMemorySize, energy_smem);

    // 0) init outputs with biases / zeros
    init_kernel<<<1024, 256>>>(gates_a, b_ih_a, b_hh_a,
                               gates_d, b_ih_d, b_hh_d,
                               pq, out_proj, b_proj, ctx);

    // 1) attention LSTM gates (split-K 8)
    mma_gemm3<<<dim3(128, 8), 128>>>(last_frame, W_ih_a,       P_, P_ + E_,
                                     att_ctx,    W_ih_a + P_,  E_, P_ + E_,
                                     att_h,      W_hh_a,       R_, R_,
                                     gates_a, 4 * R_);
    lstm_pointwise<<<(B_ * R_) / 1024, 256>>>(gates_a, att_c, ah, ac, R_);

    // 2) query projection pq = ah @ W_q^T (split-K 8)
    mma_gemm3<<<dim3(A_ / 32, 8), 128>>>(ah, W_q, R_, R_,
                                         nullptr, nullptr, 0, 0,
                                         nullptr, nullptr, 0, 0,
                                         pq, A_);

    // 3) fused conv + MMA-la + energies, then softmax
    energy_kernel<<<dim3(T_ / 64, B_), 128, energy_smem>>>(
        att_w, att_w_cum, pmem, pq, W_loc, W_lfc, W_v, energies);
    softmax_kernel<<<B_, 256>>>(energies, mask, out_w);

    // 4) context
    ctx_kernel<<<dim3(16, B_), 256>>>(out_w, memory, ctx);

    // 5) decoder LSTM gates (split-K 16)
    mma_gemm3<<<dim3(128, 16), 128>>>(ah,    W_ih_d,       R_, R_ + E_,
                                      ctx,   W_ih_d + R_,  E_, R_ + E_,
                                      dec_h, W_hh_d,       D_, D_,
                                      gates_d, 4 * D_);
    lstm_pointwise<<<(B_ * D_) / 1024, 256>>>(gates_d, dec_c, dh, dc, D_);

    // 6) output heads (proj split-K 8)
    mma_gemm3<<<dim3(H_ / 32, 8), 128>>>(dh,  W_proj,       D_, D_ + E_,
                                         ctx, W_proj + D_,  E_, D_ + E_,
                                         nullptr, nullptr, 0, 0,
                                         out_proj, H_);
    gate_kernel<<<2, 1024>>>(dh, ctx, W_gate, b_gate, out_stop);
}